// round 6
// baseline (speedup 1.0000x reference)
#include <cuda_runtime.h>
#include <math.h>

// Problem constants
#define BN   1024   // batch
#define MU   8      // memory units
#define RN   512    // neurons per unit
#define IN_  512    // input dim
#define ON   512    // output dim
#define AN   16     // attention dim
#define DN   128    // M*A
#define NSQ  20     // number of matrix squarings for spectral radius

// -------- scratch (device globals; no allocation allowed) --------
__device__ float g_P[2][MU * RN * RN];          // ping-pong squaring buffers (16 MB)
__device__ float g_nrm2[NSQ + 2][MU];           // Frobenius norm^2 per step per unit
__device__ float g_sc[MU];                      // sr[m] / rho[m]
__device__ float g_Q[BN * MU * AN];             // Q  [b][q][a]      (b*128 + q*16 + a)
__device__ float g_KV[BN * MU * 256];           // [b*8+n][ m*16+a | 128 + m*16+a ]  (K | V)
__device__ float g_Ui[BN * MU * DN];            // Ui [b][m][d]      ((b*8+m)*128 + d)

// -------- helpers --------
__device__ __forceinline__ float blockReduceSum(float v) {
    __shared__ float red[8];
    #pragma unroll
    for (int o = 16; o > 0; o >>= 1) v += __shfl_down_sync(0xffffffffu, v, o);
    int w = threadIdx.x >> 5, l = threadIdx.x & 31;
    if (l == 0) red[w] = v;
    __syncthreads();
    float r = 0.f;
    if (w == 0) {
        int nw = blockDim.x >> 5;
        r = (l < nw) ? red[l] : 0.f;
        #pragma unroll
        for (int o = 4; o > 0; o >>= 1) r += __shfl_down_sync(0xffffffffu, r, o);
    }
    return r;   // valid on thread 0
}

// -------- init: zero the norm accumulators --------
__global__ void k_init() {
    int t = threadIdx.x;
    if (t < (NSQ + 2) * MU) ((float*)g_nrm2)[t] = 0.f;
}

// -------- ||W_m||_F^2  (nrm2[0]) --------
__global__ void k_norm0(const float* __restrict__ W) {
    int m = blockIdx.y;
    const float* p = W + m * RN * RN;
    float s = 0.f;
    for (int i = blockIdx.x * blockDim.x + threadIdx.x; i < RN * RN;
         i += gridDim.x * blockDim.x) {
        float v = p[i];
        s += v * v;
    }
    float tot = blockReduceSum(s);
    if (threadIdx.x == 0) atomicAdd(&g_nrm2[0][m], tot);
}

// -------- squaring step: N_{j+1} = N_j^2 / nrm2[j]; accumulates nrm2[j+1] --------
// 128x128x8 register-tiled SGEMM, grid (4,4,8), 256 threads
__global__ void __launch_bounds__(256) k_sqr(const float* __restrict__ W, int j) {
    int m = blockIdx.z;
    const float* src = (j == 0) ? (W + m * RN * RN) : (g_P[(j - 1) & 1] + m * RN * RN);
    float* dst = g_P[j & 1] + m * RN * RN;
    float inv = 1.0f / g_nrm2[j][m];

    __shared__ float As[8][128];
    __shared__ float Bs[8][128];

    int t  = threadIdx.x;
    int tx = t & 15, ty = t >> 4;
    int arow = t >> 1, ak = (t & 1) * 4;
    int bk = t >> 5, bc = (t & 31) * 4;
    int rowBase = blockIdx.y * 128;
    int colBase = blockIdx.x * 128;

    float acc[8][8];
    #pragma unroll
    for (int i = 0; i < 8; i++)
        #pragma unroll
        for (int jj = 0; jj < 8; jj++) acc[i][jj] = 0.f;

    for (int kt = 0; kt < RN; kt += 8) {
        float4 av = *(const float4*)(src + (rowBase + arow) * RN + kt + ak);
        float4 bv = *(const float4*)(src + (kt + bk) * RN + colBase + bc);
        As[ak + 0][arow] = av.x; As[ak + 1][arow] = av.y;
        As[ak + 2][arow] = av.z; As[ak + 3][arow] = av.w;
        *(float4*)&Bs[bk][bc] = bv;
        __syncthreads();
        #pragma unroll
        for (int k = 0; k < 8; k++) {
            float4 a0 = *(const float4*)&As[k][ty * 8];
            float4 a1 = *(const float4*)&As[k][ty * 8 + 4];
            float4 b0 = *(const float4*)&Bs[k][tx * 8];
            float4 b1 = *(const float4*)&Bs[k][tx * 8 + 4];
            float ar[8] = {a0.x, a0.y, a0.z, a0.w, a1.x, a1.y, a1.z, a1.w};
            float br[8] = {b0.x, b0.y, b0.z, b0.w, b1.x, b1.y, b1.z, b1.w};
            #pragma unroll
            for (int i = 0; i < 8; i++)
                #pragma unroll
                for (int jj = 0; jj < 8; jj++) acc[i][jj] += ar[i] * br[jj];
        }
        __syncthreads();
    }

    float ss = 0.f;
    #pragma unroll
    for (int i = 0; i < 8; i++) {
        int r = rowBase + ty * 8 + i;
        #pragma unroll
        for (int jj = 0; jj < 8; jj++) {
            float c = acc[i][jj] * inv;
            dst[r * RN + colBase + tx * 8 + jj] = c;
            ss += c * c;
        }
    }
    float tot = blockReduceSum(ss);
    if (threadIdx.x == 0) atomicAdd(&g_nrm2[j + 1][m], tot);
}

// -------- finalize: rho and scale = sr/rho --------
__global__ void k_finalize(const float* __restrict__ sr) {
    int m = threadIdx.x;
    if (m < MU) {
        double acc = 0.0, w = 1.0;
        for (int j = 0; j <= NSQ; j++) {
            acc += w * 0.5 * log((double)g_nrm2[j][m]);
            w *= 0.5;
        }
        float rho = (float)exp(acc);
        g_sc[m] = sr[m] / rho;
    }
}

// -------- Q = Xi @ Wq  -> g_Q [1024 x 128], cols = (m,a) --------
// 64x64x16 tiles, grid (2,16)
__global__ void __launch_bounds__(256) k_gemmQ(const float* __restrict__ Xi,
                                               const float* __restrict__ Wq) {
    __shared__ float As[16][64];
    __shared__ float Bs[16][64];
    int t = threadIdx.x;
    int tx = t & 15, ty = t >> 4;
    int ar = t >> 2, ak = (t & 3) * 4;
    int bk = t >> 4, bc = (t & 15) * 4;
    int rb = blockIdx.y * 64, cb = blockIdx.x * 64;

    float acc[4][4];
    #pragma unroll
    for (int i = 0; i < 4; i++)
        #pragma unroll
        for (int jj = 0; jj < 4; jj++) acc[i][jj] = 0.f;

    for (int kt = 0; kt < IN_; kt += 16) {
        float4 av = *(const float4*)(Xi + (rb + ar) * IN_ + kt + ak);
        int c0 = cb + bc;
        float4 bv = *(const float4*)(Wq + (c0 >> 4) * (IN_ * AN) + (kt + bk) * AN + (c0 & 15));
        As[ak + 0][ar] = av.x; As[ak + 1][ar] = av.y;
        As[ak + 2][ar] = av.z; As[ak + 3][ar] = av.w;
        *(float4*)&Bs[bk][bc] = bv;
        __syncthreads();
        #pragma unroll
        for (int k = 0; k < 16; k++) {
            float4 a = *(const float4*)&As[k][ty * 4];
            float4 b = *(const float4*)&Bs[k][tx * 4];
            float arr[4] = {a.x, a.y, a.z, a.w};
            float brr[4] = {b.x, b.y, b.z, b.w};
            #pragma unroll
            for (int i = 0; i < 4; i++)
                #pragma unroll
                for (int jj = 0; jj < 4; jj++) acc[i][jj] += arr[i] * brr[jj];
        }
        __syncthreads();
    }
    #pragma unroll
    for (int i = 0; i < 4; i++)
        #pragma unroll
        for (int jj = 0; jj < 4; jj++)
            g_Q[(rb + ty * 4 + i) * DN + cb + tx * 4 + jj] = acc[i][jj];
}

// -------- K|V = Si @ [Wk|Wv] -> g_KV [8192 x 256] --------
// rows = (b*8+n), cols 0..127 = K(m,a), 128..255 = V(m,a). grid (4,128)
__global__ void __launch_bounds__(256) k_gemmKV(const float* __restrict__ Si,
                                                const float* __restrict__ Wk,
                                                const float* __restrict__ Wv) {
    __shared__ float As[16][64];
    __shared__ float Bs[16][64];
    int t = threadIdx.x;
    int tx = t & 15, ty = t >> 4;
    int ar = t >> 2, ak = (t & 3) * 4;
    int bk = t >> 4, bc = (t & 15) * 4;
    int rb = blockIdx.y * 64, cb = blockIdx.x * 64;

    float acc[4][4];
    #pragma unroll
    for (int i = 0; i < 4; i++)
        #pragma unroll
        for (int jj = 0; jj < 4; jj++) acc[i][jj] = 0.f;

    for (int kt = 0; kt < RN; kt += 16) {
        float4 av = *(const float4*)(Si + (rb + ar) * RN + kt + ak);
        int c0 = cb + bc;
        const float* base = (c0 < 128) ? Wk : Wv;
        int cl = c0 & 127;
        float4 bv = *(const float4*)(base + (cl >> 4) * (RN * AN) + (kt + bk) * AN + (cl & 15));
        As[ak + 0][ar] = av.x; As[ak + 1][ar] = av.y;
        As[ak + 2][ar] = av.z; As[ak + 3][ar] = av.w;
        *(float4*)&Bs[bk][bc] = bv;
        __syncthreads();
        #pragma unroll
        for (int k = 0; k < 16; k++) {
            float4 a = *(const float4*)&As[k][ty * 4];
            float4 b = *(const float4*)&Bs[k][tx * 4];
            float arr[4] = {a.x, a.y, a.z, a.w};
            float brr[4] = {b.x, b.y, b.z, b.w};
            #pragma unroll
            for (int i = 0; i < 4; i++)
                #pragma unroll
                for (int jj = 0; jj < 4; jj++) acc[i][jj] += arr[i] * brr[jj];
        }
        __syncthreads();
    }
    #pragma unroll
    for (int i = 0; i < 4; i++)
        #pragma unroll
        for (int jj = 0; jj < 4; jj++)
            g_KV[(rb + ty * 4 + i) * 256 + cb + tx * 4 + jj] = acc[i][jj];
}

// -------- attention: scores -> softmax -> /sqrt(D) -> Ui --------
// one thread per (b, m, q)
__global__ void k_attn() {
    int idx = blockIdx.x * blockDim.x + threadIdx.x;   // 0 .. 65535
    if (idx >= BN * MU * MU) return;
    int b = idx >> 6;
    int m = (idx >> 3) & 7;
    int q = idx & 7;

    float qv[AN];
    const float* Qp = g_Q + b * DN + q * AN;
    #pragma unroll
    for (int a = 0; a < AN; a++) qv[a] = Qp[a];

    float s[MU];
    #pragma unroll
    for (int n = 0; n < MU; n++) {
        const float* Kp = g_KV + (b * MU + n) * 256 + m * AN;
        float d = 0.f;
        #pragma unroll
        for (int a = 0; a < AN; a++) d += qv[a] * Kp[a];
        s[n] = d;
    }
    float mx = s[0];
    #pragma unroll
    for (int n = 1; n < MU; n++) mx = fmaxf(mx, s[n]);
    float sum = 0.f;
    #pragma unroll
    for (int n = 0; n < MU; n++) { s[n] = __expf(s[n] - mx); sum += s[n]; }
    float scale = 1.0f / (sum * sqrtf((float)DN));
    #pragma unroll
    for (int n = 0; n < MU; n++) s[n] *= scale;

    float* Up = g_Ui + (b * MU + m) * DN + q * AN;
    #pragma unroll
    for (int a = 0; a < AN; a++) {
        float u = 0.f;
        #pragma unroll
        for (int n = 0; n < MU; n++)
            u += s[n] * g_KV[(b * MU + n) * 256 + 128 + m * AN + a];
        Up[a] = u;
    }
}

// -------- state update: Snew = (1-lr)Si + lr*tanh(Ui@Win + Si@(W*sc) + bias) --------
// concat-K GEMM: [1024 x 640] @ [640 x 512] per unit m. 128x128x8 tiles, grid (4,8,8)
__global__ void __launch_bounds__(256) k_state(const float* __restrict__ Si,
                                               const float* __restrict__ Win,
                                               const float* __restrict__ W,
                                               const float* __restrict__ bias,
                                               const float* __restrict__ lr,
                                               float* __restrict__ Snew) {
    int m = blockIdx.z;
    float scm = g_sc[m];
    float lrm = lr[m];

    __shared__ float As[8][128];
    __shared__ float Bs[8][128];

    int t  = threadIdx.x;
    int tx = t & 15, ty = t >> 4;
    int arow = t >> 1, ak = (t & 1) * 4;
    int bk = t >> 5, bc = (t & 31) * 4;
    int rowBase = blockIdx.y * 128;   // batch rows
    int colBase = blockIdx.x * 128;   // neuron cols

    float acc[8][8];
    #pragma unroll
    for (int i = 0; i < 8; i++)
        #pragma unroll
        for (int jj = 0; jj < 8; jj++) acc[i][jj] = 0.f;

    for (int kt = 0; kt < DN + RN; kt += 8) {
        int kA = kt + ak;
        int brow = rowBase + arow;
        float4 av;
        if (kA < DN)
            av = *(const float4*)(g_Ui + (brow * MU + m) * DN + kA);
        else
            av = *(const float4*)(Si + brow * (MU * RN) + m * RN + (kA - DN));

        int kB = kt + bk;
        float4 bv;
        if (kB < DN) {
            bv = *(const float4*)(Win + m * (DN * RN) + kB * RN + colBase + bc);
        } else {
            bv = *(const float4*)(W + m * (RN * RN) + (kB - DN) * RN + colBase + bc);
            bv.x *= scm; bv.y *= scm; bv.z *= scm; bv.w *= scm;
        }
        As[ak + 0][arow] = av.x; As[ak + 1][arow] = av.y;
        As[ak + 2][arow] = av.z; As[ak + 3][arow] = av.w;
        *(float4*)&Bs[bk][bc] = bv;
        __syncthreads();
        #pragma unroll
        for (int k = 0; k < 8; k++) {
            float4 a0 = *(const float4*)&As[k][ty * 8];
            float4 a1 = *(const float4*)&As[k][ty * 8 + 4];
            float4 b0 = *(const float4*)&Bs[k][tx * 8];
            float4 b1 = *(const float4*)&Bs[k][tx * 8 + 4];
            float ar[8] = {a0.x, a0.y, a0.z, a0.w, a1.x, a1.y, a1.z, a1.w};
            float br[8] = {b0.x, b0.y, b0.z, b0.w, b1.x, b1.y, b1.z, b1.w};
            #pragma unroll
            for (int i = 0; i < 8; i++)
                #pragma unroll
                for (int jj = 0; jj < 8; jj++) acc[i][jj] += ar[i] * br[jj];
        }
        __syncthreads();
    }

    #pragma unroll
    for (int i = 0; i < 8; i++) {
        int b = rowBase + ty * 8 + i;
        #pragma unroll
        for (int jj = 0; jj < 8; jj++) {
            int r = colBase + tx * 8 + jj;
            float x  = acc[i][jj] + bias[m * RN + r];
            float th = tanhf(x);
            float si = Si[b * (MU * RN) + m * RN + r];
            Snew[b * (MU * RN) + m * RN + r] = (1.0f - lrm) * si + lrm * th;
        }
    }
}

// -------- Yi = Snew.reshape(B, 4096) @ Wout  [1024x512], K=4096 --------
// 64x64x16 tiles, grid (8,16)
__global__ void __launch_bounds__(256) k_gemmYi(const float* __restrict__ Snew,
                                                const float* __restrict__ Wout,
                                                float* __restrict__ Yi) {
    __shared__ float As[16][64];
    __shared__ float Bs[16][64];
    int t = threadIdx.x;
    int tx = t & 15, ty = t >> 4;
    int ar = t >> 2, ak = (t & 3) * 4;
    int bk = t >> 4, bc = (t & 15) * 4;
    int rb = blockIdx.y * 64, cb = blockIdx.x * 64;
    const int K = MU * RN;   // 4096

    float acc[4][4];
    #pragma unroll
    for (int i = 0; i < 4; i++)
        #pragma unroll
        for (int jj = 0; jj < 4; jj++) acc[i][jj] = 0.f;

    for (int kt = 0; kt < K; kt += 16) {
        float4 av = *(const float4*)(Snew + (rb + ar) * K + kt + ak);
        float4 bv = *(const float4*)(Wout + (kt + bk) * ON + cb + bc);
        As[ak + 0][ar] = av.x; As[ak + 1][ar] = av.y;
        As[ak + 2][ar] = av.z; As[ak + 3][ar] = av.w;
        *(float4*)&Bs[bk][bc] = bv;
        __syncthreads();
        #pragma unroll
        for (int k = 0; k < 16; k++) {
            float4 a = *(const float4*)&As[k][ty * 4];
            float4 b = *(const float4*)&Bs[k][tx * 4];
            float arr[4] = {a.x, a.y, a.z, a.w};
            float brr[4] = {b.x, b.y, b.z, b.w};
            #pragma unroll
            for (int i = 0; i < 4; i++)
                #pragma unroll
                for (int jj = 0; jj < 4; jj++) acc[i][jj] += arr[i] * brr[jj];
        }
        __syncthreads();
    }
    #pragma unroll
    for (int i = 0; i < 4; i++)
        #pragma unroll
        for (int jj = 0; jj < 4; jj++)
            Yi[(rb + ty * 4 + i) * ON + cb + tx * 4 + jj] = acc[i][jj];
}

// ------------------------------------------------------------------
extern "C" void kernel_launch(void* const* d_in, const int* in_sizes, int n_in,
                              void* d_out, int out_size) {
    const float* Xi   = (const float*)d_in[0];   // [1024,512]
    const float* Si   = (const float*)d_in[1];   // [1024,8,512]
    const float* Wq   = (const float*)d_in[2];   // [8,512,16]
    const float* Wk   = (const float*)d_in[3];   // [8,512,16]
    const float* Wv   = (const float*)d_in[4];   // [8,512,16]
    const float* Wout = (const float*)d_in[5];   // [4096,512]
    const float* W    = (const float*)d_in[6];   // [8,512,512]
    const float* Win  = (const float*)d_in[7];   // [8,128,512]
    const float* bias = (const float*)d_in[8];   // [8,1,512]
    const float* sr   = (const float*)d_in[9];   // [8,1,1]
    const float* lr   = (const float*)d_in[10];  // [8,1]

    float* Yi   = (float*)d_out;                 // [1024,512]
    float* Snew = (float*)d_out + BN * ON;       // [1024,8,512]

    // --- spectral radius via normalized repeated squaring ---
    k_init<<<1, 256>>>();
    k_norm0<<<dim3(16, 8), 256>>>(W);
    for (int j = 0; j < NSQ; j++)
        k_sqr<<<dim3(4, 4, 8), 256>>>(W, j);
    k_finalize<<<1, 32>>>(sr);

    // --- attention path ---
    k_gemmQ<<<dim3(2, 16), 256>>>(Xi, Wq);
    k_gemmKV<<<dim3(4, 128), 256>>>(Si, Wk, Wv);
    k_attn<<<BN * MU * MU / 256, 256>>>();

    // --- reservoir state update (fused feed+echo+tanh+leak) ---
    k_state<<<dim3(4, 8, 8), 256>>>(Si, Win, W, bias, lr, Snew);

    // --- readout ---
    k_gemmYi<<<dim3(8, 16), 256>>>(Snew, Wout, Yi);
}

// round 8
// speedup vs baseline: 1.4138x; 1.4138x over previous
#include <cuda_runtime.h>
#include <math.h>

// Problem constants
#define BN   1024   // batch
#define MU   8      // memory units
#define RN   512    // neurons per unit
#define IN_  512    // input dim
#define ON   512    // output dim
#define AN   16     // attention dim
#define DN   128    // M*A
#define NSQ  16     // number of matrix squarings for spectral radius
#define KC   16     // K-chunk for squaring GEMM

// -------- scratch (device globals; no allocation allowed) --------
__device__ float g_P[2][MU * RN * RN];          // ping-pong squaring buffers (16 MB)
__device__ float g_nrm2[NSQ + 2][MU];           // Frobenius norm^2 per step per unit
__device__ float g_sc[MU];                      // sr[m] / rho[m]
__device__ float g_Qa[BN * MU * AN];            // attention Q  [b][q][a]
__device__ float g_KV[BN * MU * 256];           // [b*8+n][ K(m,a) | V(m,a) ]
__device__ float g_Ui[BN * MU * DN];            // Ui [b][m][d]

// -------- helpers --------
__device__ __forceinline__ float blockReduceSum(float v) {
    __shared__ float red[8];
    #pragma unroll
    for (int o = 16; o > 0; o >>= 1) v += __shfl_down_sync(0xffffffffu, v, o);
    int w = threadIdx.x >> 5, l = threadIdx.x & 31;
    if (l == 0) red[w] = v;
    __syncthreads();
    float r = 0.f;
    if (w == 0) {
        int nw = blockDim.x >> 5;
        r = (l < nw) ? red[l] : 0.f;
        #pragma unroll
        for (int o = 4; o > 0; o >>= 1) r += __shfl_down_sync(0xffffffffu, r, o);
    }
    return r;   // valid on thread 0
}

// -------- init: zero the norm accumulators --------
__global__ void k_init() {
    int t = threadIdx.x;
    if (t < (NSQ + 2) * MU) ((float*)g_nrm2)[t] = 0.f;
}

// -------- ||W_m||_F^2  (nrm2[0]) --------
__global__ void k_norm0(const float* __restrict__ W) {
    int m = blockIdx.y;
    const float* p = W + m * RN * RN;
    float s = 0.f;
    for (int i = blockIdx.x * blockDim.x + threadIdx.x; i < RN * RN;
         i += gridDim.x * blockDim.x) {
        float v = p[i];
        s += v * v;
    }
    float tot = blockReduceSum(s);
    if (threadIdx.x == 0) atomicAdd(&g_nrm2[0][m], tot);
}

// ==================================================================
// Squaring step: N_{j+1} = N_j^2 / nrm2[j]; accumulates nrm2[j+1].
// 128x64 tiles, KC=16, grid (8,4,8) = 256 CTAs (2 per SM), 256 thr.
// Register-prefetch of next K-chunk overlaps global latency w/ math.
// ==================================================================
__global__ void __launch_bounds__(256, 2) k_sqr(const float* __restrict__ W, int j) {
    int m = blockIdx.z;
    const float* src = (j == 0) ? (W + m * RN * RN) : (g_P[(j - 1) & 1] + m * RN * RN);
    float* dst = g_P[j & 1] + m * RN * RN;
    float inv = 1.0f / g_nrm2[j][m];

    __shared__ float As[KC][128];   // [k][row]
    __shared__ float Bs[KC][64];    // [k][col]

    int t  = threadIdx.x;
    int tx = t & 15, ty = t >> 4;
    int rowBase = blockIdx.y * 128;
    int colBase = blockIdx.x * 64;

    // A loader: row r = t&127, k-quads kqA and kqA+2 (each 4 floats)
    int r   = t & 127;
    int kqA = t >> 7;            // 0 or 1
    // B loader: k row bkb (0..15), 4 cols at bcq
    int bkb = t >> 4;
    int bcq = (t & 15) * 4;

    float acc[8][4];
    #pragma unroll
    for (int i = 0; i < 8; i++)
        #pragma unroll
        for (int jj = 0; jj < 4; jj++) acc[i][jj] = 0.f;

    // prefetch chunk 0
    float4 pa0 = *(const float4*)(src + (rowBase + r) * RN + kqA * 4);
    float4 pa1 = *(const float4*)(src + (rowBase + r) * RN + (kqA + 2) * 4);
    float4 pb  = *(const float4*)(src + bkb * RN + colBase + bcq);

    for (int kt = 0; kt < RN; kt += KC) {
        // commit prefetched chunk to smem
        As[kqA * 4 + 0][r] = pa0.x; As[kqA * 4 + 1][r] = pa0.y;
        As[kqA * 4 + 2][r] = pa0.z; As[kqA * 4 + 3][r] = pa0.w;
        As[(kqA + 2) * 4 + 0][r] = pa1.x; As[(kqA + 2) * 4 + 1][r] = pa1.y;
        As[(kqA + 2) * 4 + 2][r] = pa1.z; As[(kqA + 2) * 4 + 3][r] = pa1.w;
        *(float4*)&Bs[bkb][bcq] = pb;
        __syncthreads();

        // prefetch next chunk (overlaps with math below)
        if (kt + KC < RN) {
            int kn = kt + KC;
            pa0 = *(const float4*)(src + (rowBase + r) * RN + kn + kqA * 4);
            pa1 = *(const float4*)(src + (rowBase + r) * RN + kn + (kqA + 2) * 4);
            pb  = *(const float4*)(src + (kn + bkb) * RN + colBase + bcq);
        }

        #pragma unroll
        for (int k = 0; k < KC; k++) {
            float4 b  = *(const float4*)&Bs[k][tx * 4];
            float4 a0 = *(const float4*)&As[k][ty * 8];
            float4 a1 = *(const float4*)&As[k][ty * 8 + 4];
            float av[8] = {a0.x, a0.y, a0.z, a0.w, a1.x, a1.y, a1.z, a1.w};
            float bv[4] = {b.x, b.y, b.z, b.w};
            #pragma unroll
            for (int i = 0; i < 8; i++)
                #pragma unroll
                for (int jj = 0; jj < 4; jj++) acc[i][jj] += av[i] * bv[jj];
        }
        __syncthreads();
    }

    float ss = 0.f;
    #pragma unroll
    for (int i = 0; i < 8; i++) {
        int gr = rowBase + ty * 8 + i;
        float4 o;
        o.x = acc[i][0] * inv; o.y = acc[i][1] * inv;
        o.z = acc[i][2] * inv; o.w = acc[i][3] * inv;
        *(float4*)(dst + gr * RN + colBase + tx * 4) = o;
        ss += o.x * o.x + o.y * o.y + o.z * o.z + o.w * o.w;
    }
    float tot = blockReduceSum(ss);
    if (threadIdx.x == 0) atomicAdd(&g_nrm2[j + 1][m], tot);
}

// -------- finalize: rho and scale = sr/rho --------
__global__ void k_finalize(const float* __restrict__ sr) {
    int m = threadIdx.x;
    if (m < MU) {
        double acc = 0.0, w = 1.0;
        for (int j = 0; j <= NSQ; j++) {
            acc += w * 0.5 * log((double)g_nrm2[j][m]);
            w *= 0.5;
        }
        float rho = (float)exp(acc);
        g_sc[m] = sr[m] / rho;
    }
}

// -------- Q = Xi @ Wq  -> g_Qa [1024 x 128] --------
__global__ void __launch_bounds__(256) k_gemmQ(const float* __restrict__ Xi,
                                               const float* __restrict__ Wq) {
    __shared__ float As[16][64];
    __shared__ float Bs[16][64];
    int t = threadIdx.x;
    int tx = t & 15, ty = t >> 4;
    int ar = t >> 2, ak = (t & 3) * 4;
    int bk = t >> 4, bc = (t & 15) * 4;
    int rb = blockIdx.y * 64, cb = blockIdx.x * 64;

    float acc[4][4];
    #pragma unroll
    for (int i = 0; i < 4; i++)
        #pragma unroll
        for (int jj = 0; jj < 4; jj++) acc[i][jj] = 0.f;

    for (int kt = 0; kt < IN_; kt += 16) {
        float4 av = *(const float4*)(Xi + (rb + ar) * IN_ + kt + ak);
        int c0 = cb + bc;
        float4 bv = *(const float4*)(Wq + (c0 >> 4) * (IN_ * AN) + (kt + bk) * AN + (c0 & 15));
        As[ak + 0][ar] = av.x; As[ak + 1][ar] = av.y;
        As[ak + 2][ar] = av.z; As[ak + 3][ar] = av.w;
        *(float4*)&Bs[bk][bc] = bv;
        __syncthreads();
        #pragma unroll
        for (int k = 0; k < 16; k++) {
            float4 a = *(const float4*)&As[k][ty * 4];
            float4 b = *(const float4*)&Bs[k][tx * 4];
            float arr[4] = {a.x, a.y, a.z, a.w};
            float brr[4] = {b.x, b.y, b.z, b.w};
            #pragma unroll
            for (int i = 0; i < 4; i++)
                #pragma unroll
                for (int jj = 0; jj < 4; jj++) acc[i][jj] += arr[i] * brr[jj];
        }
        __syncthreads();
    }
    #pragma unroll
    for (int i = 0; i < 4; i++)
        #pragma unroll
        for (int jj = 0; jj < 4; jj++)
            g_Qa[(rb + ty * 4 + i) * DN + cb + tx * 4 + jj] = acc[i][jj];
}

// -------- K|V = Si @ [Wk|Wv] -> g_KV [8192 x 256] --------
__global__ void __launch_bounds__(256) k_gemmKV(const float* __restrict__ Si,
                                                const float* __restrict__ Wk,
                                                const float* __restrict__ Wv) {
    __shared__ float As[16][64];
    __shared__ float Bs[16][64];
    int t = threadIdx.x;
    int tx = t & 15, ty = t >> 4;
    int ar = t >> 2, ak = (t & 3) * 4;
    int bk = t >> 4, bc = (t & 15) * 4;
    int rb = blockIdx.y * 64, cb = blockIdx.x * 64;

    float acc[4][4];
    #pragma unroll
    for (int i = 0; i < 4; i++)
        #pragma unroll
        for (int jj = 0; jj < 4; jj++) acc[i][jj] = 0.f;

    for (int kt = 0; kt < RN; kt += 16) {
        float4 av = *(const float4*)(Si + (rb + ar) * RN + kt + ak);
        int c0 = cb + bc;
        const float* base = (c0 < 128) ? Wk : Wv;
        int cl = c0 & 127;
        float4 bv = *(const float4*)(base + (cl >> 4) * (RN * AN) + (kt + bk) * AN + (cl & 15));
        As[ak + 0][ar] = av.x; As[ak + 1][ar] = av.y;
        As[ak + 2][ar] = av.z; As[ak + 3][ar] = av.w;
        *(float4*)&Bs[bk][bc] = bv;
        __syncthreads();
        #pragma unroll
        for (int k = 0; k < 16; k++) {
            float4 a = *(const float4*)&As[k][ty * 4];
            float4 b = *(const float4*)&Bs[k][tx * 4];
            float arr[4] = {a.x, a.y, a.z, a.w};
            float brr[4] = {b.x, b.y, b.z, b.w};
            #pragma unroll
            for (int i = 0; i < 4; i++)
                #pragma unroll
                for (int jj = 0; jj < 4; jj++) acc[i][jj] += arr[i] * brr[jj];
        }
        __syncthreads();
    }
    #pragma unroll
    for (int i = 0; i < 4; i++)
        #pragma unroll
        for (int jj = 0; jj < 4; jj++)
            g_KV[(rb + ty * 4 + i) * 256 + cb + tx * 4 + jj] = acc[i][jj];
}

// -------- attention: scores -> softmax -> /sqrt(D) -> Ui --------
__global__ void k_attn() {
    int idx = blockIdx.x * blockDim.x + threadIdx.x;
    if (idx >= BN * MU * MU) return;
    int b = idx >> 6;
    int m = (idx >> 3) & 7;
    int q = idx & 7;

    float qv[AN];
    const float* Qp = g_Qa + b * DN + q * AN;
    #pragma unroll
    for (int a = 0; a < AN; a++) qv[a] = Qp[a];

    float s[MU];
    #pragma unroll
    for (int n = 0; n < MU; n++) {
        const float* Kp = g_KV + (b * MU + n) * 256 + m * AN;
        float d = 0.f;
        #pragma unroll
        for (int a = 0; a < AN; a++) d += qv[a] * Kp[a];
        s[n] = d;
    }
    float mx = s[0];
    #pragma unroll
    for (int n = 1; n < MU; n++) mx = fmaxf(mx, s[n]);
    float sum = 0.f;
    #pragma unroll
    for (int n = 0; n < MU; n++) { s[n] = __expf(s[n] - mx); sum += s[n]; }
    float scale = 1.0f / (sum * sqrtf((float)DN));
    #pragma unroll
    for (int n = 0; n < MU; n++) s[n] *= scale;

    float* Up = g_Ui + (b * MU + m) * DN + q * AN;
    #pragma unroll
    for (int a = 0; a < AN; a++) {
        float u = 0.f;
        #pragma unroll
        for (int n = 0; n < MU; n++)
            u += s[n] * g_KV[(b * MU + n) * 256 + 128 + m * AN + a];
        Up[a] = u;
    }
}

// -------- state update: Snew = (1-lr)Si + lr*tanh(Ui@Win + Si@(W*sc) + bias) --------
__global__ void __launch_bounds__(256) k_state(const float* __restrict__ Si,
                                               const float* __restrict__ Win,
                                               const float* __restrict__ W,
                                               const float* __restrict__ bias,
                                               const float* __restrict__ lr,
                                               float* __restrict__ Snew) {
    int m = blockIdx.z;
    float scm = g_sc[m];
    float lrm = lr[m];

    __shared__ float As[8][128];
    __shared__ float Bs[8][128];

    int t  = threadIdx.x;
    int tx = t & 15, ty = t >> 4;
    int arow = t >> 1, ak = (t & 1) * 4;
    int bk = t >> 5, bc = (t & 31) * 4;
    int rowBase = blockIdx.y * 128;
    int colBase = blockIdx.x * 128;

    float acc[8][8];
    #pragma unroll
    for (int i = 0; i < 8; i++)
        #pragma unroll
        for (int jj = 0; jj < 8; jj++) acc[i][jj] = 0.f;

    for (int kt = 0; kt < DN + RN; kt += 8) {
        int kA = kt + ak;
        int brow = rowBase + arow;
        float4 av;
        if (kA < DN)
            av = *(const float4*)(g_Ui + (brow * MU + m) * DN + kA);
        else
            av = *(const float4*)(Si + brow * (MU * RN) + m * RN + (kA - DN));

        int kB = kt + bk;
        float4 bv;
        if (kB < DN) {
            bv = *(const float4*)(Win + m * (DN * RN) + kB * RN + colBase + bc);
        } else {
            bv = *(const float4*)(W + m * (RN * RN) + (kB - DN) * RN + colBase + bc);
            bv.x *= scm; bv.y *= scm; bv.z *= scm; bv.w *= scm;
        }
        As[ak + 0][arow] = av.x; As[ak + 1][arow] = av.y;
        As[ak + 2][arow] = av.z; As[ak + 3][arow] = av.w;
        *(float4*)&Bs[bk][bc] = bv;
        __syncthreads();
        #pragma unroll
        for (int k = 0; k < 8; k++) {
            float4 a0 = *(const float4*)&As[k][ty * 8];
            float4 a1 = *(const float4*)&As[k][ty * 8 + 4];
            float4 b0 = *(const float4*)&Bs[k][tx * 8];
            float4 b1 = *(const float4*)&Bs[k][tx * 8 + 4];
            float ar[8] = {a0.x, a0.y, a0.z, a0.w, a1.x, a1.y, a1.z, a1.w};
            float br[8] = {b0.x, b0.y, b0.z, b0.w, b1.x, b1.y, b1.z, b1.w};
            #pragma unroll
            for (int i = 0; i < 8; i++)
                #pragma unroll
                for (int jj = 0; jj < 8; jj++) acc[i][jj] += ar[i] * br[jj];
        }
        __syncthreads();
    }

    #pragma unroll
    for (int i = 0; i < 8; i++) {
        int b = rowBase + ty * 8 + i;
        #pragma unroll
        for (int jj = 0; jj < 8; jj++) {
            int r = colBase + tx * 8 + jj;
            float x  = acc[i][jj] + bias[m * RN + r];
            float th = tanhf(x);
            float si = Si[b * (MU * RN) + m * RN + r];
            Snew[b * (MU * RN) + m * RN + r] = (1.0f - lrm) * si + lrm * th;
        }
    }
}

// -------- Yi = Snew.reshape(B, 4096) @ Wout --------
__global__ void __launch_bounds__(256) k_gemmYi(const float* __restrict__ Snew,
                                                const float* __restrict__ Wout,
                                                float* __restrict__ Yi) {
    __shared__ float As[16][64];
    __shared__ float Bs[16][64];
    int t = threadIdx.x;
    int tx = t & 15, ty = t >> 4;
    int ar = t >> 2, ak = (t & 3) * 4;
    int bk = t >> 4, bc = (t & 15) * 4;
    int rb = blockIdx.y * 64, cb = blockIdx.x * 64;
    const int K = MU * RN;

    float acc[4][4];
    #pragma unroll
    for (int i = 0; i < 4; i++)
        #pragma unroll
        for (int jj = 0; jj < 4; jj++) acc[i][jj] = 0.f;

    for (int kt = 0; kt < K; kt += 16) {
        float4 av = *(const float4*)(Snew + (rb + ar) * K + kt + ak);
        float4 bv = *(const float4*)(Wout + (kt + bk) * ON + cb + bc);
        As[ak + 0][ar] = av.x; As[ak + 1][ar] = av.y;
        As[ak + 2][ar] = av.z; As[ak + 3][ar] = av.w;
        *(float4*)&Bs[bk][bc] = bv;
        __syncthreads();
        #pragma unroll
        for (int k = 0; k < 16; k++) {
            float4 a = *(const float4*)&As[k][ty * 4];
            float4 b = *(const float4*)&Bs[k][tx * 4];
            float arr[4] = {a.x, a.y, a.z, a.w};
            float brr[4] = {b.x, b.y, b.z, b.w};
            #pragma unroll
            for (int i = 0; i < 4; i++)
                #pragma unroll
                for (int jj = 0; jj < 4; jj++) acc[i][jj] += arr[i] * brr[jj];
        }
        __syncthreads();
    }
    #pragma unroll
    for (int i = 0; i < 4; i++)
        #pragma unroll
        for (int jj = 0; jj < 4; jj++)
            Yi[(rb + ty * 4 + i) * ON + cb + tx * 4 + jj] = acc[i][jj];
}

// ------------------------------------------------------------------
extern "C" void kernel_launch(void* const* d_in, const int* in_sizes, int n_in,
                              void* d_out, int out_size) {
    const float* Xi   = (const float*)d_in[0];
    const float* Si   = (const float*)d_in[1];
    const float* Wq   = (const float*)d_in[2];
    const float* Wk   = (const float*)d_in[3];
    const float* Wv   = (const float*)d_in[4];
    const float* Wout = (const float*)d_in[5];
    const float* W    = (const float*)d_in[6];
    const float* Win  = (const float*)d_in[7];
    const float* bias = (const float*)d_in[8];
    const float* sr   = (const float*)d_in[9];
    const float* lr   = (const float*)d_in[10];

    float* Yi   = (float*)d_out;
    float* Snew = (float*)d_out + BN * ON;

    // --- spectral radius via normalized repeated squaring ---
    k_init<<<1, 256>>>();
    k_norm0<<<dim3(16, 8), 256>>>(W);
    for (int j = 0; j < NSQ; j++)
        k_sqr<<<dim3(8, 4, 8), 256>>>(W, j);
    k_finalize<<<1, 32>>>(sr);

    // --- attention path ---
    k_gemmQ<<<dim3(2, 16), 256>>>(Xi, Wq);
    k_gemmKV<<<dim3(4, 128), 256>>>(Si, Wk, Wv);
    k_attn<<<BN * MU * MU / 256, 256>>>();

    // --- reservoir state update (fused feed+echo+tanh+leak) ---
    k_state<<<dim3(4, 8, 8), 256>>>(Si, Win, W, bias, lr, Snew);

    // --- readout ---
    k_gemmYi<<<dim3(8, 16), 256>>>(Snew, Wout, Yi);
}

// round 11
// speedup vs baseline: 1.5342x; 1.0852x over previous
#include <cuda_runtime.h>
#include <math.h>

// Problem constants
#define BN   1024   // batch
#define MU   8      // memory units
#define RN   512    // neurons per unit
#define IN_  512    // input dim
#define ON   512    // output dim
#define AN   16     // attention dim
#define DN   128    // M*A
#define NSQ  12     // number of matrix squarings for spectral radius
#define KC   16     // K-chunk for squaring GEMM

// -------- scratch (device globals; no allocation allowed) --------
__device__ float g_P[2][MU * RN * RN];          // ping-pong squaring buffers (16 MB)
__device__ float g_nrm2[NSQ + 2][MU];           // Frobenius norm^2 per step per unit
__device__ float g_sc[MU];                      // sr[m] / rho[m]
__device__ float g_Qa[BN * MU * AN];            // attention Q  [b][q][a]
__device__ float g_KV[BN * MU * 256];           // [b*8+n][ K(m,a) | V(m,a) ]
__device__ float g_Ui[BN * MU * DN];            // Ui [b][m][d]

// -------- helpers --------
__device__ __forceinline__ float blockReduceSum(float v) {
    __shared__ float red[8];
    #pragma unroll
    for (int o = 16; o > 0; o >>= 1) v += __shfl_down_sync(0xffffffffu, v, o);
    int w = threadIdx.x >> 5, l = threadIdx.x & 31;
    if (l == 0) red[w] = v;
    __syncthreads();
    float r = 0.f;
    if (w == 0) {
        int nw = blockDim.x >> 5;
        r = (l < nw) ? red[l] : 0.f;
        #pragma unroll
        for (int o = 4; o > 0; o >>= 1) r += __shfl_down_sync(0xffffffffu, r, o);
    }
    return r;   // valid on thread 0
}

// -------- init: zero the norm accumulators --------
__global__ void k_init() {
    int t = threadIdx.x;
    if (t < (NSQ + 2) * MU) ((float*)g_nrm2)[t] = 0.f;
}

// -------- ||W_m||_F^2  (nrm2[0]) --------
__global__ void k_norm0(const float* __restrict__ W) {
    int m = blockIdx.y;
    const float* p = W + m * RN * RN;
    float s = 0.f;
    for (int i = blockIdx.x * blockDim.x + threadIdx.x; i < RN * RN;
         i += gridDim.x * blockDim.x) {
        float v = p[i];
        s += v * v;
    }
    float tot = blockReduceSum(s);
    if (threadIdx.x == 0) atomicAdd(&g_nrm2[0][m], tot);
}

// ==================================================================
// Squaring step: N_{j+1} = N_j^2 / nrm2[j]; accumulates nrm2[j+1].
// 128x64 tiles, 128 threads, 8x8 register tile (LDS:FFMA = 0.25),
// KC=16 with register prefetch. grid (8,4,8) = 256 CTAs.
// ==================================================================
__global__ void __launch_bounds__(128, 4) k_sqr(const float* __restrict__ W, int j) {
    int m = blockIdx.z;
    const float* src = (j == 0) ? (W + m * RN * RN) : (g_P[(j - 1) & 1] + m * RN * RN);
    float* dst = g_P[j & 1] + m * RN * RN;
    float inv = 1.0f / g_nrm2[j][m];

    __shared__ float As[KC][128];   // [k][row]
    __shared__ float Bs[KC][64];    // [k][col]

    int t  = threadIdx.x;           // 0..127
    int tx = t & 7, ty = t >> 3;    // 8 col-groups x 16 row-groups
    int rowBase = blockIdx.y * 128;
    int colBase = blockIdx.x * 64;

    // A loader: thread t owns row t, loads its 16 k-values (4 float4)
    // B loader: 16 k-rows x 64 cols = 256 float4; thread loads f=t and f=t+128
    //   f -> k = f>>4, col4 = (f&15)*4

    float acc[8][8];
    #pragma unroll
    for (int i = 0; i < 8; i++)
        #pragma unroll
        for (int jj = 0; jj < 8; jj++) acc[i][jj] = 0.f;

    // prefetch chunk 0
    float4 pa[4], pb[2];
    #pragma unroll
    for (int q = 0; q < 4; q++)
        pa[q] = *(const float4*)(src + (rowBase + t) * RN + q * 4);
    #pragma unroll
    for (int q = 0; q < 2; q++) {
        int f = t + q * 128;
        pb[q] = *(const float4*)(src + (f >> 4) * RN + colBase + (f & 15) * 4);
    }

    for (int kt = 0; kt < RN; kt += KC) {
        // commit prefetched chunk to smem
        #pragma unroll
        for (int q = 0; q < 4; q++) {
            As[q * 4 + 0][t] = pa[q].x; As[q * 4 + 1][t] = pa[q].y;
            As[q * 4 + 2][t] = pa[q].z; As[q * 4 + 3][t] = pa[q].w;
        }
        #pragma unroll
        for (int q = 0; q < 2; q++) {
            int f = t + q * 128;
            *(float4*)&Bs[f >> 4][(f & 15) * 4] = pb[q];
        }
        __syncthreads();

        // prefetch next chunk (overlaps with math below)
        if (kt + KC < RN) {
            int kn = kt + KC;
            #pragma unroll
            for (int q = 0; q < 4; q++)
                pa[q] = *(const float4*)(src + (rowBase + t) * RN + kn + q * 4);
            #pragma unroll
            for (int q = 0; q < 2; q++) {
                int f = t + q * 128;
                pb[q] = *(const float4*)(src + (kn + (f >> 4)) * RN + colBase + (f & 15) * 4);
            }
        }

        #pragma unroll
        for (int k = 0; k < KC; k++) {
            float4 a0 = *(const float4*)&As[k][ty * 8];
            float4 a1 = *(const float4*)&As[k][ty * 8 + 4];
            float4 b0 = *(const float4*)&Bs[k][tx * 8];
            float4 b1 = *(const float4*)&Bs[k][tx * 8 + 4];
            float av[8] = {a0.x, a0.y, a0.z, a0.w, a1.x, a1.y, a1.z, a1.w};
            float bv[8] = {b0.x, b0.y, b0.z, b0.w, b1.x, b1.y, b1.z, b1.w};
            #pragma unroll
            for (int i = 0; i < 8; i++)
                #pragma unroll
                for (int jj = 0; jj < 8; jj++) acc[i][jj] += av[i] * bv[jj];
        }
        __syncthreads();
    }

    float ss = 0.f;
    #pragma unroll
    for (int i = 0; i < 8; i++) {
        int gr = rowBase + ty * 8 + i;
        float4 o0, o1;
        o0.x = acc[i][0] * inv; o0.y = acc[i][1] * inv;
        o0.z = acc[i][2] * inv; o0.w = acc[i][3] * inv;
        o1.x = acc[i][4] * inv; o1.y = acc[i][5] * inv;
        o1.z = acc[i][6] * inv; o1.w = acc[i][7] * inv;
        *(float4*)(dst + gr * RN + colBase + tx * 8)     = o0;
        *(float4*)(dst + gr * RN + colBase + tx * 8 + 4) = o1;
        ss += o0.x * o0.x + o0.y * o0.y + o0.z * o0.z + o0.w * o0.w;
        ss += o1.x * o1.x + o1.y * o1.y + o1.z * o1.z + o1.w * o1.w;
    }
    float tot = blockReduceSum(ss);
    if (threadIdx.x == 0) atomicAdd(&g_nrm2[j + 1][m], tot);
}

// -------- finalize: rho and scale = sr/rho --------
__global__ void k_finalize(const float* __restrict__ sr) {
    int m = threadIdx.x;
    if (m < MU) {
        double acc = 0.0, w = 1.0;
        for (int j = 0; j <= NSQ; j++) {
            acc += w * 0.5 * log((double)g_nrm2[j][m]);
            w *= 0.5;
        }
        float rho = (float)exp(acc);
        g_sc[m] = sr[m] / rho;
    }
}

// -------- Q = Xi @ Wq  -> g_Qa [1024 x 128] --------
__global__ void __launch_bounds__(256) k_gemmQ(const float* __restrict__ Xi,
                                               const float* __restrict__ Wq) {
    __shared__ float As[16][64];
    __shared__ float Bs[16][64];
    int t = threadIdx.x;
    int tx = t & 15, ty = t >> 4;
    int ar = t >> 2, ak = (t & 3) * 4;
    int bk = t >> 4, bc = (t & 15) * 4;
    int rb = blockIdx.y * 64, cb = blockIdx.x * 64;

    float acc[4][4];
    #pragma unroll
    for (int i = 0; i < 4; i++)
        #pragma unroll
        for (int jj = 0; jj < 4; jj++) acc[i][jj] = 0.f;

    for (int kt = 0; kt < IN_; kt += 16) {
        float4 av = *(const float4*)(Xi + (rb + ar) * IN_ + kt + ak);
        int c0 = cb + bc;
        float4 bv = *(const float4*)(Wq + (c0 >> 4) * (IN_ * AN) + (kt + bk) * AN + (c0 & 15));
        As[ak + 0][ar] = av.x; As[ak + 1][ar] = av.y;
        As[ak + 2][ar] = av.z; As[ak + 3][ar] = av.w;
        *(float4*)&Bs[bk][bc] = bv;
        __syncthreads();
        #pragma unroll
        for (int k = 0; k < 16; k++) {
            float4 a = *(const float4*)&As[k][ty * 4];
            float4 b = *(const float4*)&Bs[k][tx * 4];
            float arr[4] = {a.x, a.y, a.z, a.w};
            float brr[4] = {b.x, b.y, b.z, b.w};
            #pragma unroll
            for (int i = 0; i < 4; i++)
                #pragma unroll
                for (int jj = 0; jj < 4; jj++) acc[i][jj] += arr[i] * brr[jj];
        }
        __syncthreads();
    }
    #pragma unroll
    for (int i = 0; i < 4; i++)
        #pragma unroll
        for (int jj = 0; jj < 4; jj++)
            g_Qa[(rb + ty * 4 + i) * DN + cb + tx * 4 + jj] = acc[i][jj];
}

// -------- K|V = Si @ [Wk|Wv] -> g_KV [8192 x 256] --------
__global__ void __launch_bounds__(256) k_gemmKV(const float* __restrict__ Si,
                                                const float* __restrict__ Wk,
                                                const float* __restrict__ Wv) {
    __shared__ float As[16][64];
    __shared__ float Bs[16][64];
    int t = threadIdx.x;
    int tx = t & 15, ty = t >> 4;
    int ar = t >> 2, ak = (t & 3) * 4;
    int bk = t >> 4, bc = (t & 15) * 4;
    int rb = blockIdx.y * 64, cb = blockIdx.x * 64;

    float acc[4][4];
    #pragma unroll
    for (int i = 0; i < 4; i++)
        #pragma unroll
        for (int jj = 0; jj < 4; jj++) acc[i][jj] = 0.f;

    for (int kt = 0; kt < RN; kt += 16) {
        float4 av = *(const float4*)(Si + (rb + ar) * RN + kt + ak);
        int c0 = cb + bc;
        const float* base = (c0 < 128) ? Wk : Wv;
        int cl = c0 & 127;
        float4 bv = *(const float4*)(base + (cl >> 4) * (RN * AN) + (kt + bk) * AN + (cl & 15));
        As[ak + 0][ar] = av.x; As[ak + 1][ar] = av.y;
        As[ak + 2][ar] = av.z; As[ak + 3][ar] = av.w;
        *(float4*)&Bs[bk][bc] = bv;
        __syncthreads();
        #pragma unroll
        for (int k = 0; k < 16; k++) {
            float4 a = *(const float4*)&As[k][ty * 4];
            float4 b = *(const float4*)&Bs[k][tx * 4];
            float arr[4] = {a.x, a.y, a.z, a.w};
            float brr[4] = {b.x, b.y, b.z, b.w};
            #pragma unroll
            for (int i = 0; i < 4; i++)
                #pragma unroll
                for (int jj = 0; jj < 4; jj++) acc[i][jj] += arr[i] * brr[jj];
        }
        __syncthreads();
    }
    #pragma unroll
    for (int i = 0; i < 4; i++)
        #pragma unroll
        for (int jj = 0; jj < 4; jj++)
            g_KV[(rb + ty * 4 + i) * 256 + cb + tx * 4 + jj] = acc[i][jj];
}

// -------- attention: scores -> softmax -> /sqrt(D) -> Ui --------
__global__ void k_attn() {
    int idx = blockIdx.x * blockDim.x + threadIdx.x;
    if (idx >= BN * MU * MU) return;
    int b = idx >> 6;
    int m = (idx >> 3) & 7;
    int q = idx & 7;

    float qv[AN];
    const float* Qp = g_Qa + b * DN + q * AN;
    #pragma unroll
    for (int a = 0; a < AN; a++) qv[a] = Qp[a];

    float s[MU];
    #pragma unroll
    for (int n = 0; n < MU; n++) {
        const float* Kp = g_KV + (b * MU + n) * 256 + m * AN;
        float d = 0.f;
        #pragma unroll
        for (int a = 0; a < AN; a++) d += qv[a] * Kp[a];
        s[n] = d;
    }
    float mx = s[0];
    #pragma unroll
    for (int n = 1; n < MU; n++) mx = fmaxf(mx, s[n]);
    float sum = 0.f;
    #pragma unroll
    for (int n = 0; n < MU; n++) { s[n] = __expf(s[n] - mx); sum += s[n]; }
    float scale = 1.0f / (sum * sqrtf((float)DN));
    #pragma unroll
    for (int n = 0; n < MU; n++) s[n] *= scale;

    float* Up = g_Ui + (b * MU + m) * DN + q * AN;
    #pragma unroll
    for (int a = 0; a < AN; a++) {
        float u = 0.f;
        #pragma unroll
        for (int n = 0; n < MU; n++)
            u += s[n] * g_KV[(b * MU + n) * 256 + 128 + m * AN + a];
        Up[a] = u;
    }
}

// -------- state update: Snew = (1-lr)Si + lr*tanh(Ui@Win + Si@(W*sc) + bias) --------
__global__ void __launch_bounds__(256) k_state(const float* __restrict__ Si,
                                               const float* __restrict__ Win,
                                               const float* __restrict__ W,
                                               const float* __restrict__ bias,
                                               const float* __restrict__ lr,
                                               float* __restrict__ Snew) {
    int m = blockIdx.z;
    float scm = g_sc[m];
    float lrm = lr[m];

    __shared__ float As[8][128];
    __shared__ float Bs[8][128];

    int t  = threadIdx.x;
    int tx = t & 15, ty = t >> 4;
    int arow = t >> 1, ak = (t & 1) * 4;
    int bk = t >> 5, bc = (t & 31) * 4;
    int rowBase = blockIdx.y * 128;
    int colBase = blockIdx.x * 128;

    float acc[8][8];
    #pragma unroll
    for (int i = 0; i < 8; i++)
        #pragma unroll
        for (int jj = 0; jj < 8; jj++) acc[i][jj] = 0.f;

    for (int kt = 0; kt < DN + RN; kt += 8) {
        int kA = kt + ak;
        int brow = rowBase + arow;
        float4 av;
        if (kA < DN)
            av = *(const float4*)(g_Ui + (brow * MU + m) * DN + kA);
        else
            av = *(const float4*)(Si + brow * (MU * RN) + m * RN + (kA - DN));

        int kB = kt + bk;
        float4 bv;
        if (kB < DN) {
            bv = *(const float4*)(Win + m * (DN * RN) + kB * RN + colBase + bc);
        } else {
            bv = *(const float4*)(W + m * (RN * RN) + (kB - DN) * RN + colBase + bc);
            bv.x *= scm; bv.y *= scm; bv.z *= scm; bv.w *= scm;
        }
        As[ak + 0][arow] = av.x; As[ak + 1][arow] = av.y;
        As[ak + 2][arow] = av.z; As[ak + 3][arow] = av.w;
        *(float4*)&Bs[bk][bc] = bv;
        __syncthreads();
        #pragma unroll
        for (int k = 0; k < 8; k++) {
            float4 a0 = *(const float4*)&As[k][ty * 8];
            float4 a1 = *(const float4*)&As[k][ty * 8 + 4];
            float4 b0 = *(const float4*)&Bs[k][tx * 8];
            float4 b1 = *(const float4*)&Bs[k][tx * 8 + 4];
            float ar[8] = {a0.x, a0.y, a0.z, a0.w, a1.x, a1.y, a1.z, a1.w};
            float br[8] = {b0.x, b0.y, b0.z, b0.w, b1.x, b1.y, b1.z, b1.w};
            #pragma unroll
            for (int i = 0; i < 8; i++)
                #pragma unroll
                for (int jj = 0; jj < 8; jj++) acc[i][jj] += ar[i] * br[jj];
        }
        __syncthreads();
    }

    #pragma unroll
    for (int i = 0; i < 8; i++) {
        int b = rowBase + ty * 8 + i;
        #pragma unroll
        for (int jj = 0; jj < 8; jj++) {
            int r = colBase + tx * 8 + jj;
            float x  = acc[i][jj] + bias[m * RN + r];
            float th = tanhf(x);
            float si = Si[b * (MU * RN) + m * RN + r];
            Snew[b * (MU * RN) + m * RN + r] = (1.0f - lrm) * si + lrm * th;
        }
    }
}

// -------- Yi = Snew.reshape(B, 4096) @ Wout --------
__global__ void __launch_bounds__(256) k_gemmYi(const float* __restrict__ Snew,
                                                const float* __restrict__ Wout,
                                                float* __restrict__ Yi) {
    __shared__ float As[16][64];
    __shared__ float Bs[16][64];
    int t = threadIdx.x;
    int tx = t & 15, ty = t >> 4;
    int ar = t >> 2, ak = (t & 3) * 4;
    int bk = t >> 4, bc = (t & 15) * 4;
    int rb = blockIdx.y * 64, cb = blockIdx.x * 64;
    const int K = MU * RN;

    float acc[4][4];
    #pragma unroll
    for (int i = 0; i < 4; i++)
        #pragma unroll
        for (int jj = 0; jj < 4; jj++) acc[i][jj] = 0.f;

    for (int kt = 0; kt < K; kt += 16) {
        float4 av = *(const float4*)(Snew + (rb + ar) * K + kt + ak);
        float4 bv = *(const float4*)(Wout + (kt + bk) * ON + cb + bc);
        As[ak + 0][ar] = av.x; As[ak + 1][ar] = av.y;
        As[ak + 2][ar] = av.z; As[ak + 3][ar] = av.w;
        *(float4*)&Bs[bk][bc] = bv;
        __syncthreads();
        #pragma unroll
        for (int k = 0; k < 16; k++) {
            float4 a = *(const float4*)&As[k][ty * 4];
            float4 b = *(const float4*)&Bs[k][tx * 4];
            float arr[4] = {a.x, a.y, a.z, a.w};
            float brr[4] = {b.x, b.y, b.z, b.w};
            #pragma unroll
            for (int i = 0; i < 4; i++)
                #pragma unroll
                for (int jj = 0; jj < 4; jj++) acc[i][jj] += arr[i] * brr[jj];
        }
        __syncthreads();
    }
    #pragma unroll
    for (int i = 0; i < 4; i++)
        #pragma unroll
        for (int jj = 0; jj < 4; jj++)
            Yi[(rb + ty * 4 + i) * ON + cb + tx * 4 + jj] = acc[i][jj];
}

// ------------------------------------------------------------------
extern "C" void kernel_launch(void* const* d_in, const int* in_sizes, int n_in,
                              void* d_out, int out_size) {
    const float* Xi   = (const float*)d_in[0];
    const float* Si   = (const float*)d_in[1];
    const float* Wq   = (const float*)d_in[2];
    const float* Wk   = (const float*)d_in[3];
    const float* Wv   = (const float*)d_in[4];
    const float* Wout = (const float*)d_in[5];
    const float* W    = (const float*)d_in[6];
    const float* Win  = (const float*)d_in[7];
    const float* bias = (const float*)d_in[8];
    const float* sr   = (const float*)d_in[9];
    const float* lr   = (const float*)d_in[10];

    float* Yi   = (float*)d_out;
    float* Snew = (float*)d_out + BN * ON;

    // --- spectral radius via normalized repeated squaring ---
    k_init<<<1, 256>>>();
    k_norm0<<<dim3(16, 8), 256>>>(W);
    for (int j = 0; j < NSQ; j++)
        k_sqr<<<dim3(8, 4, 8), 128>>>(W, j);
    k_finalize<<<1, 32>>>(sr);

    // --- attention path ---
    k_gemmQ<<<dim3(2, 16), 256>>>(Xi, Wq);
    k_gemmKV<<<dim3(4, 128), 256>>>(Si, Wk, Wv);
    k_attn<<<BN * MU * MU / 256, 256>>>();

    // --- reservoir state update (fused feed+echo+tanh+leak) ---
    k_state<<<dim3(4, 8, 8), 256>>>(Si, Win, W, bias, lr, Snew);

    // --- readout ---
    k_gemmYi<<<dim3(8, 16), 256>>>(Snew, Wout, Yi);
}

// round 13
// speedup vs baseline: 1.6991x; 1.1075x over previous
#include <cuda_runtime.h>
#include <math.h>
#include <stdint.h>

// Problem constants
#define BN   1024   // batch
#define MU   8      // memory units
#define RN   512    // neurons per unit
#define IN_  512    // input dim
#define ON   512    // output dim
#define AN   16     // attention dim
#define DN   128    // M*A
#define NSQ  11     // number of matrix squarings for spectral radius
#define KC   16     // K-chunk for squaring GEMM

// -------- scratch (device globals; no allocation allowed) --------
__device__ float g_P[2][MU * RN * RN];          // ping-pong squaring buffers (16 MB)
__device__ float g_nrm2[NSQ + 2][MU];           // Frobenius norm^2 per step per unit
__device__ float g_sc[MU];                      // sr[m] / rho[m]
__device__ float g_Qa[BN * MU * AN];            // attention Q  [b][q][a]
__device__ float g_KV[BN * MU * 256];           // [b*8+n][ K(m,a) | V(m,a) ]
__device__ float g_Ui[BN * MU * DN];            // Ui [b][m][d]

// -------- packed f32x2 helpers --------
__device__ __forceinline__ void ffma2(uint64_t& d, uint64_t a, uint64_t b) {
    asm("fma.rn.f32x2 %0, %1, %2, %0;" : "+l"(d) : "l"(a), "l"(b));
}
__device__ __forceinline__ uint64_t pack2(float lo, float hi) {
    uint64_t r;
    asm("mov.b64 %0, {%1, %2};" : "=l"(r) : "f"(lo), "f"(hi));
    return r;
}
__device__ __forceinline__ void unpack2(uint64_t v, float& lo, float& hi) {
    asm("mov.b64 {%0, %1}, %2;" : "=f"(lo), "=f"(hi) : "l"(v));
}

// -------- helpers --------
__device__ __forceinline__ float blockReduceSum(float v) {
    __shared__ float red[8];
    #pragma unroll
    for (int o = 16; o > 0; o >>= 1) v += __shfl_down_sync(0xffffffffu, v, o);
    int w = threadIdx.x >> 5, l = threadIdx.x & 31;
    if (l == 0) red[w] = v;
    __syncthreads();
    float r = 0.f;
    if (w == 0) {
        int nw = blockDim.x >> 5;
        r = (l < nw) ? red[l] : 0.f;
        #pragma unroll
        for (int o = 4; o > 0; o >>= 1) r += __shfl_down_sync(0xffffffffu, r, o);
    }
    return r;   // valid on thread 0
}

// -------- init: zero the norm accumulators --------
__global__ void k_init() {
    int t = threadIdx.x;
    if (t < (NSQ + 2) * MU) ((float*)g_nrm2)[t] = 0.f;
}

// -------- ||W_m||_F^2  (nrm2[0]) --------
__global__ void k_norm0(const float* __restrict__ W) {
    int m = blockIdx.y;
    const float* p = W + m * RN * RN;
    float s = 0.f;
    for (int i = blockIdx.x * blockDim.x + threadIdx.x; i < RN * RN;
         i += gridDim.x * blockDim.x) {
        float v = p[i];
        s += v * v;
    }
    float tot = blockReduceSum(s);
    if (threadIdx.x == 0) atomicAdd(&g_nrm2[0][m], tot);
}

// ==================================================================
// Squaring step: N_{j+1} = N_j^2 / nrm2[j]; accumulates nrm2[j+1].
// 128x64 tiles, 128 threads, 8x8 register tile, packed f32x2 FMA
// (acc pairs along rows). KC=16 with register prefetch. grid 256.
// ==================================================================
__global__ void __launch_bounds__(128, 2) k_sqr(const float* __restrict__ W, int j) {
    int m = blockIdx.z;
    const float* src = (j == 0) ? (W + m * RN * RN) : (g_P[(j - 1) & 1] + m * RN * RN);
    float* dst = g_P[j & 1] + m * RN * RN;
    float inv = 1.0f / g_nrm2[j][m];

    __shared__ float As[KC][128];   // [k][row]
    __shared__ float Bs[KC][64];    // [k][col]

    int t  = threadIdx.x;           // 0..127
    int tx = t & 7, ty = t >> 3;    // 8 col-groups x 16 row-groups
    int rowBase = blockIdx.y * 128;
    int colBase = blockIdx.x * 64;

    // acc[p][jj]: rows (ty*8+2p, ty*8+2p+1), col tx*8+jj
    uint64_t acc[4][8];
    #pragma unroll
    for (int p = 0; p < 4; p++)
        #pragma unroll
        for (int jj = 0; jj < 8; jj++) acc[p][jj] = 0ull;

    // prefetch chunk 0
    float4 pa[4], pb[2];
    #pragma unroll
    for (int q = 0; q < 4; q++)
        pa[q] = *(const float4*)(src + (rowBase + t) * RN + q * 4);
    #pragma unroll
    for (int q = 0; q < 2; q++) {
        int f = t + q * 128;
        pb[q] = *(const float4*)(src + (f >> 4) * RN + colBase + (f & 15) * 4);
    }

    for (int kt = 0; kt < RN; kt += KC) {
        // commit prefetched chunk to smem
        #pragma unroll
        for (int q = 0; q < 4; q++) {
            As[q * 4 + 0][t] = pa[q].x; As[q * 4 + 1][t] = pa[q].y;
            As[q * 4 + 2][t] = pa[q].z; As[q * 4 + 3][t] = pa[q].w;
        }
        #pragma unroll
        for (int q = 0; q < 2; q++) {
            int f = t + q * 128;
            *(float4*)&Bs[f >> 4][(f & 15) * 4] = pb[q];
        }
        __syncthreads();

        // prefetch next chunk (overlaps with math below)
        if (kt + KC < RN) {
            int kn = kt + KC;
            #pragma unroll
            for (int q = 0; q < 4; q++)
                pa[q] = *(const float4*)(src + (rowBase + t) * RN + kn + q * 4);
            #pragma unroll
            for (int q = 0; q < 2; q++) {
                int f = t + q * 128;
                pb[q] = *(const float4*)(src + (kn + (f >> 4)) * RN + colBase + (f & 15) * 4);
            }
        }

        #pragma unroll
        for (int k = 0; k < KC; k++) {
            float4 a0 = *(const float4*)&As[k][ty * 8];
            float4 a1 = *(const float4*)&As[k][ty * 8 + 4];
            float4 b0 = *(const float4*)&Bs[k][tx * 8];
            float4 b1 = *(const float4*)&Bs[k][tx * 8 + 4];
            uint64_t ap[4];
            ap[0] = pack2(a0.x, a0.y); ap[1] = pack2(a0.z, a0.w);
            ap[2] = pack2(a1.x, a1.y); ap[3] = pack2(a1.z, a1.w);
            uint64_t bb[8];
            bb[0] = pack2(b0.x, b0.x); bb[1] = pack2(b0.y, b0.y);
            bb[2] = pack2(b0.z, b0.z); bb[3] = pack2(b0.w, b0.w);
            bb[4] = pack2(b1.x, b1.x); bb[5] = pack2(b1.y, b1.y);
            bb[6] = pack2(b1.z, b1.z); bb[7] = pack2(b1.w, b1.w);
            #pragma unroll
            for (int p = 0; p < 4; p++)
                #pragma unroll
                for (int jj = 0; jj < 8; jj++) ffma2(acc[p][jj], ap[p], bb[jj]);
        }
        __syncthreads();
    }

    float ss = 0.f;
    #pragma unroll
    for (int p = 0; p < 4; p++) {
        float lo[8], hi[8];
        #pragma unroll
        for (int jj = 0; jj < 8; jj++) {
            unpack2(acc[p][jj], lo[jj], hi[jj]);
            lo[jj] *= inv; hi[jj] *= inv;
        }
        int gr0 = rowBase + ty * 8 + 2 * p;
        float4 o;
        o.x = lo[0]; o.y = lo[1]; o.z = lo[2]; o.w = lo[3];
        *(float4*)(dst + gr0 * RN + colBase + tx * 8) = o;
        ss += o.x * o.x + o.y * o.y + o.z * o.z + o.w * o.w;
        o.x = lo[4]; o.y = lo[5]; o.z = lo[6]; o.w = lo[7];
        *(float4*)(dst + gr0 * RN + colBase + tx * 8 + 4) = o;
        ss += o.x * o.x + o.y * o.y + o.z * o.z + o.w * o.w;
        o.x = hi[0]; o.y = hi[1]; o.z = hi[2]; o.w = hi[3];
        *(float4*)(dst + (gr0 + 1) * RN + colBase + tx * 8) = o;
        ss += o.x * o.x + o.y * o.y + o.z * o.z + o.w * o.w;
        o.x = hi[4]; o.y = hi[5]; o.z = hi[6]; o.w = hi[7];
        *(float4*)(dst + (gr0 + 1) * RN + colBase + tx * 8 + 4) = o;
        ss += o.x * o.x + o.y * o.y + o.z * o.z + o.w * o.w;
    }
    float tot = blockReduceSum(ss);
    if (threadIdx.x == 0) atomicAdd(&g_nrm2[j + 1][m], tot);
}

// -------- finalize: rho and scale = sr/rho --------
__global__ void k_finalize(const float* __restrict__ sr) {
    int m = threadIdx.x;
    if (m < MU) {
        double acc = 0.0, w = 1.0;
        for (int j = 0; j <= NSQ; j++) {
            acc += w * 0.5 * log((double)g_nrm2[j][m]);
            w *= 0.5;
        }
        float rho = (float)exp(acc);
        g_sc[m] = sr[m] / rho;
    }
}

// -------- Q = Xi @ Wq  -> g_Qa [1024 x 128] --------
__global__ void __launch_bounds__(256) k_gemmQ(const float* __restrict__ Xi,
                                               const float* __restrict__ Wq) {
    __shared__ float As[16][64];
    __shared__ float Bs[16][64];
    int t = threadIdx.x;
    int tx = t & 15, ty = t >> 4;
    int ar = t >> 2, ak = (t & 3) * 4;
    int bk = t >> 4, bc = (t & 15) * 4;
    int rb = blockIdx.y * 64, cb = blockIdx.x * 64;

    float acc[4][4];
    #pragma unroll
    for (int i = 0; i < 4; i++)
        #pragma unroll
        for (int jj = 0; jj < 4; jj++) acc[i][jj] = 0.f;

    for (int kt = 0; kt < IN_; kt += 16) {
        float4 av = *(const float4*)(Xi + (rb + ar) * IN_ + kt + ak);
        int c0 = cb + bc;
        float4 bv = *(const float4*)(Wq + (c0 >> 4) * (IN_ * AN) + (kt + bk) * AN + (c0 & 15));
        As[ak + 0][ar] = av.x; As[ak + 1][ar] = av.y;
        As[ak + 2][ar] = av.z; As[ak + 3][ar] = av.w;
        *(float4*)&Bs[bk][bc] = bv;
        __syncthreads();
        #pragma unroll
        for (int k = 0; k < 16; k++) {
            float4 a = *(const float4*)&As[k][ty * 4];
            float4 b = *(const float4*)&Bs[k][tx * 4];
            float arr[4] = {a.x, a.y, a.z, a.w};
            float brr[4] = {b.x, b.y, b.z, b.w};
            #pragma unroll
            for (int i = 0; i < 4; i++)
                #pragma unroll
                for (int jj = 0; jj < 4; jj++) acc[i][jj] += arr[i] * brr[jj];
        }
        __syncthreads();
    }
    #pragma unroll
    for (int i = 0; i < 4; i++)
        #pragma unroll
        for (int jj = 0; jj < 4; jj++)
            g_Qa[(rb + ty * 4 + i) * DN + cb + tx * 4 + jj] = acc[i][jj];
}

// -------- K|V = Si @ [Wk|Wv] -> g_KV [8192 x 256] --------
__global__ void __launch_bounds__(256) k_gemmKV(const float* __restrict__ Si,
                                                const float* __restrict__ Wk,
                                                const float* __restrict__ Wv) {
    __shared__ float As[16][64];
    __shared__ float Bs[16][64];
    int t = threadIdx.x;
    int tx = t & 15, ty = t >> 4;
    int ar = t >> 2, ak = (t & 3) * 4;
    int bk = t >> 4, bc = (t & 15) * 4;
    int rb = blockIdx.y * 64, cb = blockIdx.x * 64;

    float acc[4][4];
    #pragma unroll
    for (int i = 0; i < 4; i++)
        #pragma unroll
        for (int jj = 0; jj < 4; jj++) acc[i][jj] = 0.f;

    for (int kt = 0; kt < RN; kt += 16) {
        float4 av = *(const float4*)(Si + (rb + ar) * RN + kt + ak);
        int c0 = cb + bc;
        const float* base = (c0 < 128) ? Wk : Wv;
        int cl = c0 & 127;
        float4 bv = *(const float4*)(base + (cl >> 4) * (RN * AN) + (kt + bk) * AN + (cl & 15));
        As[ak + 0][ar] = av.x; As[ak + 1][ar] = av.y;
        As[ak + 2][ar] = av.z; As[ak + 3][ar] = av.w;
        *(float4*)&Bs[bk][bc] = bv;
        __syncthreads();
        #pragma unroll
        for (int k = 0; k < 16; k++) {
            float4 a = *(const float4*)&As[k][ty * 4];
            float4 b = *(const float4*)&Bs[k][tx * 4];
            float arr[4] = {a.x, a.y, a.z, a.w};
            float brr[4] = {b.x, b.y, b.z, b.w};
            #pragma unroll
            for (int i = 0; i < 4; i++)
                #pragma unroll
                for (int jj = 0; jj < 4; jj++) acc[i][jj] += arr[i] * brr[jj];
        }
        __syncthreads();
    }
    #pragma unroll
    for (int i = 0; i < 4; i++)
        #pragma unroll
        for (int jj = 0; jj < 4; jj++)
            g_KV[(rb + ty * 4 + i) * 256 + cb + tx * 4 + jj] = acc[i][jj];
}

// -------- attention: scores -> softmax -> /sqrt(D) -> Ui --------
__global__ void k_attn() {
    int idx = blockIdx.x * blockDim.x + threadIdx.x;
    if (idx >= BN * MU * MU) return;
    int b = idx >> 6;
    int m = (idx >> 3) & 7;
    int q = idx & 7;

    float qv[AN];
    const float* Qp = g_Qa + b * DN + q * AN;
    #pragma unroll
    for (int a = 0; a < AN; a++) qv[a] = Qp[a];

    float s[MU];
    #pragma unroll
    for (int n = 0; n < MU; n++) {
        const float* Kp = g_KV + (b * MU + n) * 256 + m * AN;
        float d = 0.f;
        #pragma unroll
        for (int a = 0; a < AN; a++) d += qv[a] * Kp[a];
        s[n] = d;
    }
    float mx = s[0];
    #pragma unroll
    for (int n = 1; n < MU; n++) mx = fmaxf(mx, s[n]);
    float sum = 0.f;
    #pragma unroll
    for (int n = 0; n < MU; n++) { s[n] = __expf(s[n] - mx); sum += s[n]; }
    float scale = 1.0f / (sum * sqrtf((float)DN));
    #pragma unroll
    for (int n = 0; n < MU; n++) s[n] *= scale;

    float* Up = g_Ui + (b * MU + m) * DN + q * AN;
    #pragma unroll
    for (int a = 0; a < AN; a++) {
        float u = 0.f;
        #pragma unroll
        for (int n = 0; n < MU; n++)
            u += s[n] * g_KV[(b * MU + n) * 256 + 128 + m * AN + a];
        Up[a] = u;
    }
}

// -------- state update: Snew = (1-lr)Si + lr*tanh(Ui@Win + Si@(W*sc) + bias) --------
// concat-K GEMM with packed f32x2 accumulation (pairs along batch rows)
__global__ void __launch_bounds__(256, 2) k_state(const float* __restrict__ Si,
                                                  const float* __restrict__ Win,
                                                  const float* __restrict__ W,
                                                  const float* __restrict__ bias,
                                                  const float* __restrict__ lr,
                                                  float* __restrict__ Snew) {
    int m = blockIdx.z;
    float scm = g_sc[m];
    float lrm = lr[m];

    __shared__ float As[8][128];
    __shared__ float Bs[8][128];

    int t  = threadIdx.x;
    int tx = t & 15, ty = t >> 4;
    int arow = t >> 1, ak = (t & 1) * 4;
    int bk = t >> 5, bc = (t & 31) * 4;
    int rowBase = blockIdx.y * 128;
    int colBase = blockIdx.x * 128;

    // acc[p][jj]: rows (ty*8+2p, +1), col tx*8+jj
    uint64_t acc[4][8];
    #pragma unroll
    for (int p = 0; p < 4; p++)
        #pragma unroll
        for (int jj = 0; jj < 8; jj++) acc[p][jj] = 0ull;

    for (int kt = 0; kt < DN + RN; kt += 8) {
        int kA = kt + ak;
        int brow = rowBase + arow;
        float4 av;
        if (kA < DN)
            av = *(const float4*)(g_Ui + (brow * MU + m) * DN + kA);
        else
            av = *(const float4*)(Si + brow * (MU * RN) + m * RN + (kA - DN));

        int kB = kt + bk;
        float4 bv;
        if (kB < DN) {
            bv = *(const float4*)(Win + m * (DN * RN) + kB * RN + colBase + bc);
        } else {
            bv = *(const float4*)(W + m * (RN * RN) + (kB - DN) * RN + colBase + bc);
            bv.x *= scm; bv.y *= scm; bv.z *= scm; bv.w *= scm;
        }
        As[ak + 0][arow] = av.x; As[ak + 1][arow] = av.y;
        As[ak + 2][arow] = av.z; As[ak + 3][arow] = av.w;
        *(float4*)&Bs[bk][bc] = bv;
        __syncthreads();
        #pragma unroll
        for (int k = 0; k < 8; k++) {
            float4 a0 = *(const float4*)&As[k][ty * 8];
            float4 a1 = *(const float4*)&As[k][ty * 8 + 4];
            float4 b0 = *(const float4*)&Bs[k][tx * 8];
            float4 b1 = *(const float4*)&Bs[k][tx * 8 + 4];
            uint64_t ap[4];
            ap[0] = pack2(a0.x, a0.y); ap[1] = pack2(a0.z, a0.w);
            ap[2] = pack2(a1.x, a1.y); ap[3] = pack2(a1.z, a1.w);
            uint64_t bb[8];
            bb[0] = pack2(b0.x, b0.x); bb[1] = pack2(b0.y, b0.y);
            bb[2] = pack2(b0.z, b0.z); bb[3] = pack2(b0.w, b0.w);
            bb[4] = pack2(b1.x, b1.x); bb[5] = pack2(b1.y, b1.y);
            bb[6] = pack2(b1.z, b1.z); bb[7] = pack2(b1.w, b1.w);
            #pragma unroll
            for (int p = 0; p < 4; p++)
                #pragma unroll
                for (int jj = 0; jj < 8; jj++) ffma2(acc[p][jj], ap[p], bb[jj]);
        }
        __syncthreads();
    }

    #pragma unroll
    for (int p = 0; p < 4; p++) {
        #pragma unroll
        for (int half = 0; half < 2; half++) {
            int b = rowBase + ty * 8 + 2 * p + half;
            #pragma unroll
            for (int jj = 0; jj < 8; jj++) {
                int r = colBase + tx * 8 + jj;
                float lo, hi;
                unpack2(acc[p][jj], lo, hi);
                float x = (half ? hi : lo) + bias[m * RN + r];
                float th = tanhf(x);
                float si = Si[b * (MU * RN) + m * RN + r];
                Snew[b * (MU * RN) + m * RN + r] = (1.0f - lrm) * si + lrm * th;
            }
        }
    }
}

// -------- Yi = Snew.reshape(B, 4096) @ Wout --------
__global__ void __launch_bounds__(256) k_gemmYi(const float* __restrict__ Snew,
                                                const float* __restrict__ Wout,
                                                float* __restrict__ Yi) {
    __shared__ float As[16][64];
    __shared__ float Bs[16][64];
    int t = threadIdx.x;
    int tx = t & 15, ty = t >> 4;
    int ar = t >> 2, ak = (t & 3) * 4;
    int bk = t >> 4, bc = (t & 15) * 4;
    int rb = blockIdx.y * 64, cb = blockIdx.x * 64;
    const int K = MU * RN;

    float acc[4][4];
    #pragma unroll
    for (int i = 0; i < 4; i++)
        #pragma unroll
        for (int jj = 0; jj < 4; jj++) acc[i][jj] = 0.f;

    for (int kt = 0; kt < K; kt += 16) {
        float4 av = *(const float4*)(Snew + (rb + ar) * K + kt + ak);
        float4 bv = *(const float4*)(Wout + (kt + bk) * ON + cb + bc);
        As[ak + 0][ar] = av.x; As[ak + 1][ar] = av.y;
        As[ak + 2][ar] = av.z; As[ak + 3][ar] = av.w;
        *(float4*)&Bs[bk][bc] = bv;
        __syncthreads();
        #pragma unroll
        for (int k = 0; k < 16; k++) {
            float4 a = *(const float4*)&As[k][ty * 4];
            float4 b = *(const float4*)&Bs[k][tx * 4];
            float arr[4] = {a.x, a.y, a.z, a.w};
            float brr[4] = {b.x, b.y, b.z, b.w};
            #pragma unroll
            for (int i = 0; i < 4; i++)
                #pragma unroll
                for (int jj = 0; jj < 4; jj++) acc[i][jj] += arr[i] * brr[jj];
        }
        __syncthreads();
    }
    #pragma unroll
    for (int i = 0; i < 4; i++)
        #pragma unroll
        for (int jj = 0; jj < 4; jj++)
            Yi[(rb + ty * 4 + i) * ON + cb + tx * 4 + jj] = acc[i][jj];
}

// ------------------------------------------------------------------
extern "C" void kernel_launch(void* const* d_in, const int* in_sizes, int n_in,
                              void* d_out, int out_size) {
    const float* Xi   = (const float*)d_in[0];
    const float* Si   = (const float*)d_in[1];
    const float* Wq   = (const float*)d_in[2];
    const float* Wk   = (const float*)d_in[3];
    const float* Wv   = (const float*)d_in[4];
    const float* Wout = (const float*)d_in[5];
    const float* W    = (const float*)d_in[6];
    const float* Win  = (const float*)d_in[7];
    const float* bias = (const float*)d_in[8];
    const float* sr   = (const float*)d_in[9];
    const float* lr   = (const float*)d_in[10];

    float* Yi   = (float*)d_out;
    float* Snew = (float*)d_out + BN * ON;

    // --- spectral radius via normalized repeated squaring ---
    k_init<<<1, 256>>>();
    k_norm0<<<dim3(16, 8), 256>>>(W);
    for (int j = 0; j < NSQ; j++)
        k_sqr<<<dim3(8, 4, 8), 128>>>(W, j);
    k_finalize<<<1, 32>>>(sr);

    // --- attention path ---
    k_gemmQ<<<dim3(2, 16), 256>>>(Xi, Wq);
    k_gemmKV<<<dim3(4, 128), 256>>>(Si, Wk, Wv);
    k_attn<<<BN * MU * MU / 256, 256>>>();

    // --- reservoir state update (fused feed+echo+tanh+leak) ---
    k_state<<<dim3(4, 8, 8), 256>>>(Si, Win, W, bias, lr, Snew);

    // --- readout ---
    k_gemmYi<<<dim3(8, 16), 256>>>(Snew, Wout, Yi);
}

// round 15
// speedup vs baseline: 1.9643x; 1.1561x over previous
#include <cuda_runtime.h>
#include <math.h>
#include <stdint.h>

// Problem constants
#define BN   1024   // batch
#define MU   8      // memory units
#define RN   512    // neurons per unit
#define IN_  512    // input dim
#define ON   512    // output dim
#define AN   16     // attention dim
#define DN   128    // M*A
#define NSQ  10     // number of matrix squarings for spectral radius
#define KC   16     // K-chunk for squaring/state GEMMs

// -------- scratch (device globals; no allocation allowed) --------
__device__ float g_P[2][MU * RN * RN];          // ping-pong squaring buffers (16 MB)
__device__ float g_nrm2[NSQ + 2][MU];           // Frobenius norm^2 per step per unit
__device__ float g_sc[MU];                      // sr[m] / rho[m]
__device__ float g_Qa[BN * MU * AN];            // attention Q  [b][q][a]
__device__ float g_KV[BN * MU * 256];           // [b*8+n][ K(m,a) | V(m,a) ]
__device__ float g_Ui[BN * MU * DN];            // Ui [b][m][d]

// -------- packed f32x2 helpers --------
__device__ __forceinline__ void ffma2(uint64_t& d, uint64_t a, uint64_t b) {
    asm("fma.rn.f32x2 %0, %1, %2, %0;" : "+l"(d) : "l"(a), "l"(b));
}
__device__ __forceinline__ uint64_t pack2(float lo, float hi) {
    uint64_t r;
    asm("mov.b64 %0, {%1, %2};" : "=l"(r) : "f"(lo), "f"(hi));
    return r;
}
__device__ __forceinline__ void unpack2(uint64_t v, float& lo, float& hi) {
    asm("mov.b64 {%0, %1}, %2;" : "=f"(lo), "=f"(hi) : "l"(v));
}

// -------- helpers --------
__device__ __forceinline__ float blockReduceSum(float v) {
    __shared__ float red[8];
    #pragma unroll
    for (int o = 16; o > 0; o >>= 1) v += __shfl_down_sync(0xffffffffu, v, o);
    int w = threadIdx.x >> 5, l = threadIdx.x & 31;
    if (l == 0) red[w] = v;
    __syncthreads();
    float r = 0.f;
    if (w == 0) {
        int nw = blockDim.x >> 5;
        r = (l < nw) ? red[l] : 0.f;
        #pragma unroll
        for (int o = 4; o > 0; o >>= 1) r += __shfl_down_sync(0xffffffffu, r, o);
    }
    return r;   // valid on thread 0
}

// -------- init: zero the norm accumulators --------
__global__ void k_init() {
    int t = threadIdx.x;
    if (t < (NSQ + 2) * MU) ((float*)g_nrm2)[t] = 0.f;
}

// -------- ||W_m||_F^2  (nrm2[0]) --------
__global__ void k_norm0(const float* __restrict__ W) {
    int m = blockIdx.y;
    const float* p = W + m * RN * RN;
    float s = 0.f;
    for (int i = blockIdx.x * blockDim.x + threadIdx.x; i < RN * RN;
         i += gridDim.x * blockDim.x) {
        float v = p[i];
        s += v * v;
    }
    float tot = blockReduceSum(s);
    if (threadIdx.x == 0) atomicAdd(&g_nrm2[0][m], tot);
}

// ==================================================================
// Squaring step: N_{j+1} = N_j^2 / nrm2[j]; accumulates nrm2[j+1].
// 128x128 tile, 256 threads, 8x8 acc as f32x2 col-pairs.
// LDS (128 cyc) == ffma2 (128 cyc) per k-iter per SM: balanced.
// grid (4,4,8) = 128 CTAs (single wave, 1 CTA/SM).
// ==================================================================
__global__ void __launch_bounds__(256, 1) k_sqr(const float* __restrict__ W, int j) {
    int m = blockIdx.z;
    const float* src = (j == 0) ? (W + m * RN * RN) : (g_P[(j - 1) & 1] + m * RN * RN);
    float* dst = g_P[j & 1] + m * RN * RN;
    float inv = 1.0f / g_nrm2[j][m];

    __shared__ float As[KC][128];   // [k][row]
    __shared__ float Bs[KC][128];   // [k][col]

    int t  = threadIdx.x;           // 0..255
    int tx = t & 15, ty = t >> 4;   // 16 col-groups x 16 row-groups (8 wide each)
    int rowBase = blockIdx.y * 128;
    int colBase = blockIdx.x * 128;

    // A loader: row ar, k-offsets aq..aq+7 (2 float4 along k, row-major src)
    int ar = t & 127;
    int aq = (t >> 7) * 8;          // 0 or 8
    // B loader: f = t + q*256 -> k = f>>5, col4 = (f&31)*4

    // acc[i][jp]: row ty*8+i, cols (tx*8 + 2jp, +1)
    uint64_t acc[8][4];
    #pragma unroll
    for (int i = 0; i < 8; i++)
        #pragma unroll
        for (int jp = 0; jp < 4; jp++) acc[i][jp] = 0ull;

    // prefetch chunk 0
    float4 pa[2], pb[2];
    #pragma unroll
    for (int q = 0; q < 2; q++)
        pa[q] = *(const float4*)(src + (rowBase + ar) * RN + aq + q * 4);
    #pragma unroll
    for (int q = 0; q < 2; q++) {
        int f = t + q * 256;
        pb[q] = *(const float4*)(src + (f >> 5) * RN + colBase + (f & 31) * 4);
    }

    for (int kt = 0; kt < RN; kt += KC) {
        // commit prefetched chunk to smem
        #pragma unroll
        for (int q = 0; q < 2; q++) {
            As[aq + q * 4 + 0][ar] = pa[q].x; As[aq + q * 4 + 1][ar] = pa[q].y;
            As[aq + q * 4 + 2][ar] = pa[q].z; As[aq + q * 4 + 3][ar] = pa[q].w;
        }
        #pragma unroll
        for (int q = 0; q < 2; q++) {
            int f = t + q * 256;
            *(float4*)&Bs[f >> 5][(f & 31) * 4] = pb[q];
        }
        __syncthreads();

        // prefetch next chunk (overlaps with math below)
        if (kt + KC < RN) {
            int kn = kt + KC;
            #pragma unroll
            for (int q = 0; q < 2; q++)
                pa[q] = *(const float4*)(src + (rowBase + ar) * RN + kn + aq + q * 4);
            #pragma unroll
            for (int q = 0; q < 2; q++) {
                int f = t + q * 256;
                pb[q] = *(const float4*)(src + (kn + (f >> 5)) * RN + colBase + (f & 31) * 4);
            }
        }

        #pragma unroll
        for (int k = 0; k < KC; k++) {
            float4 a0 = *(const float4*)&As[k][ty * 8];
            float4 a1 = *(const float4*)&As[k][ty * 8 + 4];
            float4 b0 = *(const float4*)&Bs[k][tx * 8];
            float4 b1 = *(const float4*)&Bs[k][tx * 8 + 4];
            uint64_t bp[4];
            bp[0] = pack2(b0.x, b0.y); bp[1] = pack2(b0.z, b0.w);
            bp[2] = pack2(b1.x, b1.y); bp[3] = pack2(b1.z, b1.w);
            float av[8] = {a0.x, a0.y, a0.z, a0.w, a1.x, a1.y, a1.z, a1.w};
            #pragma unroll
            for (int i = 0; i < 8; i++) {
                uint64_t ai = pack2(av[i], av[i]);
                #pragma unroll
                for (int jp = 0; jp < 4; jp++) ffma2(acc[i][jp], ai, bp[jp]);
            }
        }
        __syncthreads();
    }

    float ss = 0.f;
    #pragma unroll
    for (int i = 0; i < 8; i++) {
        int gr = rowBase + ty * 8 + i;
        float c[8];
        #pragma unroll
        for (int jp = 0; jp < 4; jp++) {
            unpack2(acc[i][jp], c[2 * jp], c[2 * jp + 1]);
            c[2 * jp] *= inv; c[2 * jp + 1] *= inv;
        }
        float4 o0 = make_float4(c[0], c[1], c[2], c[3]);
        float4 o1 = make_float4(c[4], c[5], c[6], c[7]);
        *(float4*)(dst + gr * RN + colBase + tx * 8)     = o0;
        *(float4*)(dst + gr * RN + colBase + tx * 8 + 4) = o1;
        ss += o0.x * o0.x + o0.y * o0.y + o0.z * o0.z + o0.w * o0.w;
        ss += o1.x * o1.x + o1.y * o1.y + o1.z * o1.z + o1.w * o1.w;
    }
    float tot = blockReduceSum(ss);
    if (threadIdx.x == 0) atomicAdd(&g_nrm2[j + 1][m], tot);
}

// -------- finalize: rho and scale = sr/rho --------
__global__ void k_finalize(const float* __restrict__ sr) {
    int m = threadIdx.x;
    if (m < MU) {
        double acc = 0.0, w = 1.0;
        for (int j = 0; j <= NSQ; j++) {
            acc += w * 0.5 * log((double)g_nrm2[j][m]);
            w *= 0.5;
        }
        float rho = (float)exp(acc);
        g_sc[m] = sr[m] / rho;
    }
}

// -------- Q = Xi @ Wq  -> g_Qa [1024 x 128] --------
__global__ void __launch_bounds__(256) k_gemmQ(const float* __restrict__ Xi,
                                               const float* __restrict__ Wq) {
    __shared__ float As[16][64];
    __shared__ float Bs[16][64];
    int t = threadIdx.x;
    int tx = t & 15, ty = t >> 4;
    int ar = t >> 2, ak = (t & 3) * 4;
    int bk = t >> 4, bc = (t & 15) * 4;
    int rb = blockIdx.y * 64, cb = blockIdx.x * 64;

    float acc[4][4];
    #pragma unroll
    for (int i = 0; i < 4; i++)
        #pragma unroll
        for (int jj = 0; jj < 4; jj++) acc[i][jj] = 0.f;

    for (int kt = 0; kt < IN_; kt += 16) {
        float4 av = *(const float4*)(Xi + (rb + ar) * IN_ + kt + ak);
        int c0 = cb + bc;
        float4 bv = *(const float4*)(Wq + (c0 >> 4) * (IN_ * AN) + (kt + bk) * AN + (c0 & 15));
        As[ak + 0][ar] = av.x; As[ak + 1][ar] = av.y;
        As[ak + 2][ar] = av.z; As[ak + 3][ar] = av.w;
        *(float4*)&Bs[bk][bc] = bv;
        __syncthreads();
        #pragma unroll
        for (int k = 0; k < 16; k++) {
            float4 a = *(const float4*)&As[k][ty * 4];
            float4 b = *(const float4*)&Bs[k][tx * 4];
            float arr[4] = {a.x, a.y, a.z, a.w};
            float brr[4] = {b.x, b.y, b.z, b.w};
            #pragma unroll
            for (int i = 0; i < 4; i++)
                #pragma unroll
                for (int jj = 0; jj < 4; jj++) acc[i][jj] += arr[i] * brr[jj];
        }
        __syncthreads();
    }
    #pragma unroll
    for (int i = 0; i < 4; i++)
        #pragma unroll
        for (int jj = 0; jj < 4; jj++)
            g_Qa[(rb + ty * 4 + i) * DN + cb + tx * 4 + jj] = acc[i][jj];
}

// -------- K|V = Si @ [Wk|Wv] -> g_KV [8192 x 256] --------
__global__ void __launch_bounds__(256) k_gemmKV(const float* __restrict__ Si,
                                                const float* __restrict__ Wk,
                                                const float* __restrict__ Wv) {
    __shared__ float As[16][64];
    __shared__ float Bs[16][64];
    int t = threadIdx.x;
    int tx = t & 15, ty = t >> 4;
    int ar = t >> 2, ak = (t & 3) * 4;
    int bk = t >> 4, bc = (t & 15) * 4;
    int rb = blockIdx.y * 64, cb = blockIdx.x * 64;

    float acc[4][4];
    #pragma unroll
    for (int i = 0; i < 4; i++)
        #pragma unroll
        for (int jj = 0; jj < 4; jj++) acc[i][jj] = 0.f;

    for (int kt = 0; kt < RN; kt += 16) {
        float4 av = *(const float4*)(Si + (rb + ar) * RN + kt + ak);
        int c0 = cb + bc;
        const float* base = (c0 < 128) ? Wk : Wv;
        int cl = c0 & 127;
        float4 bv = *(const float4*)(base + (cl >> 4) * (RN * AN) + (kt + bk) * AN + (cl & 15));
        As[ak + 0][ar] = av.x; As[ak + 1][ar] = av.y;
        As[ak + 2][ar] = av.z; As[ak + 3][ar] = av.w;
        *(float4*)&Bs[bk][bc] = bv;
        __syncthreads();
        #pragma unroll
        for (int k = 0; k < 16; k++) {
            float4 a = *(const float4*)&As[k][ty * 4];
            float4 b = *(const float4*)&Bs[k][tx * 4];
            float arr[4] = {a.x, a.y, a.z, a.w};
            float brr[4] = {b.x, b.y, b.z, b.w};
            #pragma unroll
            for (int i = 0; i < 4; i++)
                #pragma unroll
                for (int jj = 0; jj < 4; jj++) acc[i][jj] += arr[i] * brr[jj];
        }
        __syncthreads();
    }
    #pragma unroll
    for (int i = 0; i < 4; i++)
        #pragma unroll
        for (int jj = 0; jj < 4; jj++)
            g_KV[(rb + ty * 4 + i) * 256 + cb + tx * 4 + jj] = acc[i][jj];
}

// -------- attention: scores -> softmax -> /sqrt(D) -> Ui --------
__global__ void k_attn() {
    int idx = blockIdx.x * blockDim.x + threadIdx.x;
    if (idx >= BN * MU * MU) return;
    int b = idx >> 6;
    int m = (idx >> 3) & 7;
    int q = idx & 7;

    float qv[AN];
    const float* Qp = g_Qa + b * DN + q * AN;
    #pragma unroll
    for (int a = 0; a < AN; a++) qv[a] = Qp[a];

    float s[MU];
    #pragma unroll
    for (int n = 0; n < MU; n++) {
        const float* Kp = g_KV + (b * MU + n) * 256 + m * AN;
        float d = 0.f;
        #pragma unroll
        for (int a = 0; a < AN; a++) d += qv[a] * Kp[a];
        s[n] = d;
    }
    float mx = s[0];
    #pragma unroll
    for (int n = 1; n < MU; n++) mx = fmaxf(mx, s[n]);
    float sum = 0.f;
    #pragma unroll
    for (int n = 0; n < MU; n++) { s[n] = __expf(s[n] - mx); sum += s[n]; }
    float scale = 1.0f / (sum * sqrtf((float)DN));
    #pragma unroll
    for (int n = 0; n < MU; n++) s[n] *= scale;

    float* Up = g_Ui + (b * MU + m) * DN + q * AN;
    #pragma unroll
    for (int a = 0; a < AN; a++) {
        float u = 0.f;
        #pragma unroll
        for (int n = 0; n < MU; n++)
            u += s[n] * g_KV[(b * MU + n) * 256 + 128 + m * AN + a];
        Up[a] = u;
    }
}

// -------- state update: Snew = (1-lr)Si + lr*tanh(Ui@Win + Si@(W*sc) + bias) --------
// concat-K GEMM, KC=16, 8x8 acc as f32x2 col-pairs. grid (4,8,8), 256 thr.
__global__ void __launch_bounds__(256, 2) k_state(const float* __restrict__ Si,
                                                  const float* __restrict__ Win,
                                                  const float* __restrict__ W,
                                                  const float* __restrict__ bias,
                                                  const float* __restrict__ lr,
                                                  float* __restrict__ Snew) {
    int m = blockIdx.z;
    float scm = g_sc[m];
    float lrm = lr[m];

    __shared__ float As[KC][128];
    __shared__ float Bs[KC][128];

    int t  = threadIdx.x;
    int tx = t & 15, ty = t >> 4;
    int rowBase = blockIdx.y * 128;
    int colBase = blockIdx.x * 128;

    int ar = t & 127;
    int aq = (t >> 7) * 8;

    uint64_t acc[8][4];
    #pragma unroll
    for (int i = 0; i < 8; i++)
        #pragma unroll
        for (int jp = 0; jp < 4; jp++) acc[i][jp] = 0ull;

    for (int kt = 0; kt < DN + RN; kt += KC) {
        // A tile: rows=batch, k = kt..kt+15 (whole chunk in one region; DN%KC==0)
        #pragma unroll
        for (int q = 0; q < 2; q++) {
            int kA = kt + aq + q * 4;
            int brow = rowBase + ar;
            float4 av;
            if (kA < DN)
                av = *(const float4*)(g_Ui + (brow * MU + m) * DN + kA);
            else
                av = *(const float4*)(Si + brow * (MU * RN) + m * RN + (kA - DN));
            As[aq + q * 4 + 0][ar] = av.x; As[aq + q * 4 + 1][ar] = av.y;
            As[aq + q * 4 + 2][ar] = av.z; As[aq + q * 4 + 3][ar] = av.w;
        }
        // B tile
        #pragma unroll
        for (int q = 0; q < 2; q++) {
            int f = t + q * 256;
            int kB = kt + (f >> 5);
            int c4 = (f & 31) * 4;
            float4 bv;
            if (kB < DN) {
                bv = *(const float4*)(Win + m * (DN * RN) + kB * RN + colBase + c4);
            } else {
                bv = *(const float4*)(W + m * (RN * RN) + (kB - DN) * RN + colBase + c4);
                bv.x *= scm; bv.y *= scm; bv.z *= scm; bv.w *= scm;
            }
            *(float4*)&Bs[f >> 5][c4] = bv;
        }
        __syncthreads();

        #pragma unroll
        for (int k = 0; k < KC; k++) {
            float4 a0 = *(const float4*)&As[k][ty * 8];
            float4 a1 = *(const float4*)&As[k][ty * 8 + 4];
            float4 b0 = *(const float4*)&Bs[k][tx * 8];
            float4 b1 = *(const float4*)&Bs[k][tx * 8 + 4];
            uint64_t bp[4];
            bp[0] = pack2(b0.x, b0.y); bp[1] = pack2(b0.z, b0.w);
            bp[2] = pack2(b1.x, b1.y); bp[3] = pack2(b1.z, b1.w);
            float av[8] = {a0.x, a0.y, a0.z, a0.w, a1.x, a1.y, a1.z, a1.w};
            #pragma unroll
            for (int i = 0; i < 8; i++) {
                uint64_t ai = pack2(av[i], av[i]);
                #pragma unroll
                for (int jp = 0; jp < 4; jp++) ffma2(acc[i][jp], ai, bp[jp]);
            }
        }
        __syncthreads();
    }

    #pragma unroll
    for (int i = 0; i < 8; i++) {
        int b = rowBase + ty * 8 + i;
        #pragma unroll
        for (int jp = 0; jp < 4; jp++) {
            float lo, hi;
            unpack2(acc[i][jp], lo, hi);
            int r0 = colBase + tx * 8 + 2 * jp;
            float x0 = lo + bias[m * RN + r0];
            float x1 = hi + bias[m * RN + r0 + 1];
            float s0 = Si[b * (MU * RN) + m * RN + r0];
            float s1 = Si[b * (MU * RN) + m * RN + r0 + 1];
            Snew[b * (MU * RN) + m * RN + r0]     = (1.0f - lrm) * s0 + lrm * tanhf(x0);
            Snew[b * (MU * RN) + m * RN + r0 + 1] = (1.0f - lrm) * s1 + lrm * tanhf(x1);
        }
    }
}

// -------- Yi = Snew.reshape(B, 4096) @ Wout --------
__global__ void __launch_bounds__(256) k_gemmYi(const float* __restrict__ Snew,
                                                const float* __restrict__ Wout,
                                                float* __restrict__ Yi) {
    __shared__ float As[16][64];
    __shared__ float Bs[16][64];
    int t = threadIdx.x;
    int tx = t & 15, ty = t >> 4;
    int ar = t >> 2, ak = (t & 3) * 4;
    int bk = t >> 4, bc = (t & 15) * 4;
    int rb = blockIdx.y * 64, cb = blockIdx.x * 64;
    const int K = MU * RN;

    float acc[4][4];
    #pragma unroll
    for (int i = 0; i < 4; i++)
        #pragma unroll
        for (int jj = 0; jj < 4; jj++) acc[i][jj] = 0.f;

    for (int kt = 0; kt < K; kt += 16) {
        float4 av = *(const float4*)(Snew + (rb + ar) * K + kt + ak);
        float4 bv = *(const float4*)(Wout + (kt + bk) * ON + cb + bc);
        As[ak + 0][ar] = av.x; As[ak + 1][ar] = av.y;
        As[ak + 2][ar] = av.z; As[ak + 3][ar] = av.w;
        *(float4*)&Bs[bk][bc] = bv;
        __syncthreads();
        #pragma unroll
        for (int k = 0; k < 16; k++) {
            float4 a = *(const float4*)&As[k][ty * 4];
            float4 b = *(const float4*)&Bs[k][tx * 4];
            float arr[4] = {a.x, a.y, a.z, a.w};
            float brr[4] = {b.x, b.y, b.z, b.w};
            #pragma unroll
            for (int i = 0; i < 4; i++)
                #pragma unroll
                for (int jj = 0; jj < 4; jj++) acc[i][jj] += arr[i] * brr[jj];
        }
        __syncthreads();
    }
    #pragma unroll
    for (int i = 0; i < 4; i++)
        #pragma unroll
        for (int jj = 0; jj < 4; jj++)
            Yi[(rb + ty * 4 + i) * ON + cb + tx * 4 + jj] = acc[i][jj];
}

// ------------------------------------------------------------------
extern "C" void kernel_launch(void* const* d_in, const int* in_sizes, int n_in,
                              void* d_out, int out_size) {
    const float* Xi   = (const float*)d_in[0];
    const float* Si   = (const float*)d_in[1];
    const float* Wq   = (const float*)d_in[2];
    const float* Wk   = (const float*)d_in[3];
    const float* Wv   = (const float*)d_in[4];
    const float* Wout = (const float*)d_in[5];
    const float* W    = (const float*)d_in[6];
    const float* Win  = (const float*)d_in[7];
    const float* bias = (const float*)d_in[8];
    const float* sr   = (const float*)d_in[9];
    const float* lr   = (const float*)d_in[10];

    float* Yi   = (float*)d_out;
    float* Snew = (float*)d_out + BN * ON;

    // --- spectral radius via normalized repeated squaring ---
    k_init<<<1, 256>>>();
    k_norm0<<<dim3(16, 8), 256>>>(W);
    for (int j = 0; j < NSQ; j++)
        k_sqr<<<dim3(4, 4, 8), 256>>>(W, j);
    k_finalize<<<1, 32>>>(sr);

    // --- attention path ---
    k_gemmQ<<<dim3(2, 16), 256>>>(Xi, Wq);
    k_gemmKV<<<dim3(4, 128), 256>>>(Si, Wk, Wv);
    k_attn<<<BN * MU * MU / 256, 256>>>();

    // --- reservoir state update (fused feed+echo+tanh+leak) ---
    k_state<<<dim3(4, 8, 8), 256>>>(Si, Win, W, bias, lr, Snew);

    // --- readout ---
    k_gemmYi<<<dim3(8, 16), 256>>>(Snew, Wout, Yi);
}

// round 16
// speedup vs baseline: 2.2041x; 1.1220x over previous
#include <cuda_runtime.h>
#include <math.h>
#include <stdint.h>

// Problem constants
#define BN   1024   // batch
#define MU   8      // memory units
#define RN   512    // neurons per unit
#define IN_  512    // input dim
#define ON   512    // output dim
#define AN   16     // attention dim
#define DN   128    // M*A
#define NSQ  10     // number of matrix squarings for spectral radius
#define KC   16     // K-chunk for squaring/state GEMMs

// -------- scratch (device globals; no allocation allowed) --------
__device__ float g_P[2][MU * RN * RN];          // ping-pong squaring buffers (16 MB)
__device__ float g_Yp[4][BN * ON];              // split-K partials for Yi (8 MB)
__device__ float g_nrm2[NSQ + 2][MU];           // Frobenius norm^2 per step per unit
__device__ float g_sc[MU];                      // sr[m] / rho[m]
__device__ float g_Qa[BN * MU * AN];            // attention Q  [b][q][a]
__device__ float g_KV[BN * MU * 256];           // [b*8+n][ K(m,a) | V(m,a) ]
__device__ float g_Ui[BN * MU * DN];            // Ui [b][m][d]

// -------- packed f32x2 helpers --------
__device__ __forceinline__ void ffma2(uint64_t& d, uint64_t a, uint64_t b) {
    asm("fma.rn.f32x2 %0, %1, %2, %0;" : "+l"(d) : "l"(a), "l"(b));
}
__device__ __forceinline__ uint64_t pack2(float lo, float hi) {
    uint64_t r;
    asm("mov.b64 %0, {%1, %2};" : "=l"(r) : "f"(lo), "f"(hi));
    return r;
}
__device__ __forceinline__ void unpack2(uint64_t v, float& lo, float& hi) {
    asm("mov.b64 {%0, %1}, %2;" : "=f"(lo), "=f"(hi) : "l"(v));
}

// -------- helpers --------
__device__ __forceinline__ float blockReduceSum(float v) {
    __shared__ float red[8];
    #pragma unroll
    for (int o = 16; o > 0; o >>= 1) v += __shfl_down_sync(0xffffffffu, v, o);
    int w = threadIdx.x >> 5, l = threadIdx.x & 31;
    if (l == 0) red[w] = v;
    __syncthreads();
    float r = 0.f;
    if (w == 0) {
        int nw = blockDim.x >> 5;
        r = (l < nw) ? red[l] : 0.f;
        #pragma unroll
        for (int o = 4; o > 0; o >>= 1) r += __shfl_down_sync(0xffffffffu, r, o);
    }
    return r;   // valid on thread 0
}

// -------- init: zero the norm accumulators --------
__global__ void k_init() {
    int t = threadIdx.x;
    if (t < (NSQ + 2) * MU) ((float*)g_nrm2)[t] = 0.f;
}

// -------- ||W_m||_F^2  (nrm2[0]) --------
__global__ void k_norm0(const float* __restrict__ W) {
    int m = blockIdx.y;
    const float* p = W + m * RN * RN;
    float s = 0.f;
    for (int i = blockIdx.x * blockDim.x + threadIdx.x; i < RN * RN;
         i += gridDim.x * blockDim.x) {
        float v = p[i];
        s += v * v;
    }
    float tot = blockReduceSum(s);
    if (threadIdx.x == 0) atomicAdd(&g_nrm2[0][m], tot);
}

// ==================================================================
// Squaring step: N_{j+1} = N_j^2 / nrm2[j]; accumulates nrm2[j+1].
// 128x128 tile, 256 threads, 8x8 acc as f32x2 col-pairs.
// DOUBLE-BUFFERED smem: one __syncthreads per chunk.
// grid (4,4,8) = 128 CTAs (single wave, 1 CTA/SM).
// ==================================================================
__global__ void __launch_bounds__(256, 1) k_sqr(const float* __restrict__ W, int j) {
    int m = blockIdx.z;
    const float* src = (j == 0) ? (W + m * RN * RN) : (g_P[(j - 1) & 1] + m * RN * RN);
    float* dst = g_P[j & 1] + m * RN * RN;
    float inv = 1.0f / g_nrm2[j][m];

    __shared__ float As[2][KC][128];   // [buf][k][row]
    __shared__ float Bs[2][KC][128];   // [buf][k][col]

    int t  = threadIdx.x;           // 0..255
    int tx = t & 15, ty = t >> 4;
    int rowBase = blockIdx.y * 128;
    int colBase = blockIdx.x * 128;

    int ar = t & 127;
    int aq = (t >> 7) * 8;          // 0 or 8

    uint64_t acc[8][4];
    #pragma unroll
    for (int i = 0; i < 8; i++)
        #pragma unroll
        for (int jp = 0; jp < 4; jp++) acc[i][jp] = 0ull;

    // load chunk 0, commit to buf 0
    float4 pa[2], pb[2];
    #pragma unroll
    for (int q = 0; q < 2; q++)
        pa[q] = *(const float4*)(src + (rowBase + ar) * RN + aq + q * 4);
    #pragma unroll
    for (int q = 0; q < 2; q++) {
        int f = t + q * 256;
        pb[q] = *(const float4*)(src + (f >> 5) * RN + colBase + (f & 31) * 4);
    }
    #pragma unroll
    for (int q = 0; q < 2; q++) {
        As[0][aq + q * 4 + 0][ar] = pa[q].x; As[0][aq + q * 4 + 1][ar] = pa[q].y;
        As[0][aq + q * 4 + 2][ar] = pa[q].z; As[0][aq + q * 4 + 3][ar] = pa[q].w;
        int f = t + q * 256;
        *(float4*)&Bs[0][f >> 5][(f & 31) * 4] = pb[q];
    }
    __syncthreads();

    const int NCH = RN / KC;   // 32
    for (int c = 0; c < NCH; c++) {
        int buf = c & 1, nxt = buf ^ 1;
        // issue next chunk's LDGs before math (latency hidden by 2048-cyc math)
        if (c + 1 < NCH) {
            int kn = (c + 1) * KC;
            #pragma unroll
            for (int q = 0; q < 2; q++)
                pa[q] = *(const float4*)(src + (rowBase + ar) * RN + kn + aq + q * 4);
            #pragma unroll
            for (int q = 0; q < 2; q++) {
                int f = t + q * 256;
                pb[q] = *(const float4*)(src + (kn + (f >> 5)) * RN + colBase + (f & 31) * 4);
            }
        }

        #pragma unroll
        for (int k = 0; k < KC; k++) {
            float4 a0 = *(const float4*)&As[buf][k][ty * 8];
            float4 a1 = *(const float4*)&As[buf][k][ty * 8 + 4];
            float4 b0 = *(const float4*)&Bs[buf][k][tx * 8];
            float4 b1 = *(const float4*)&Bs[buf][k][tx * 8 + 4];
            uint64_t bp[4];
            bp[0] = pack2(b0.x, b0.y); bp[1] = pack2(b0.z, b0.w);
            bp[2] = pack2(b1.x, b1.y); bp[3] = pack2(b1.z, b1.w);
            float av[8] = {a0.x, a0.y, a0.z, a0.w, a1.x, a1.y, a1.z, a1.w};
            #pragma unroll
            for (int i = 0; i < 8; i++) {
                uint64_t ai = pack2(av[i], av[i]);
                #pragma unroll
                for (int jp = 0; jp < 4; jp++) ffma2(acc[i][jp], ai, bp[jp]);
            }
        }

        // commit next chunk to the other buffer (no read conflict)
        if (c + 1 < NCH) {
            #pragma unroll
            for (int q = 0; q < 2; q++) {
                As[nxt][aq + q * 4 + 0][ar] = pa[q].x;
                As[nxt][aq + q * 4 + 1][ar] = pa[q].y;
                As[nxt][aq + q * 4 + 2][ar] = pa[q].z;
                As[nxt][aq + q * 4 + 3][ar] = pa[q].w;
                int f = t + q * 256;
                *(float4*)&Bs[nxt][f >> 5][(f & 31) * 4] = pb[q];
            }
        }
        __syncthreads();
    }

    float ss = 0.f;
    #pragma unroll
    for (int i = 0; i < 8; i++) {
        int gr = rowBase + ty * 8 + i;
        float cv[8];
        #pragma unroll
        for (int jp = 0; jp < 4; jp++) {
            unpack2(acc[i][jp], cv[2 * jp], cv[2 * jp + 1]);
            cv[2 * jp] *= inv; cv[2 * jp + 1] *= inv;
        }
        float4 o0 = make_float4(cv[0], cv[1], cv[2], cv[3]);
        float4 o1 = make_float4(cv[4], cv[5], cv[6], cv[7]);
        *(float4*)(dst + gr * RN + colBase + tx * 8)     = o0;
        *(float4*)(dst + gr * RN + colBase + tx * 8 + 4) = o1;
        ss += o0.x * o0.x + o0.y * o0.y + o0.z * o0.z + o0.w * o0.w;
        ss += o1.x * o1.x + o1.y * o1.y + o1.z * o1.z + o1.w * o1.w;
    }
    float tot = blockReduceSum(ss);
    if (threadIdx.x == 0) atomicAdd(&g_nrm2[j + 1][m], tot);
}

// -------- finalize: rho and scale = sr/rho --------
__global__ void k_finalize(const float* __restrict__ sr) {
    int m = threadIdx.x;
    if (m < MU) {
        double acc = 0.0, w = 1.0;
        for (int j = 0; j <= NSQ; j++) {
            acc += w * 0.5 * log((double)g_nrm2[j][m]);
            w *= 0.5;
        }
        float rho = (float)exp(acc);
        g_sc[m] = sr[m] / rho;
    }
}

// -------- Q = Xi @ Wq  -> g_Qa [1024 x 128] --------
__global__ void __launch_bounds__(256) k_gemmQ(const float* __restrict__ Xi,
                                               const float* __restrict__ Wq) {
    __shared__ float As[16][64];
    __shared__ float Bs[16][64];
    int t = threadIdx.x;
    int tx = t & 15, ty = t >> 4;
    int ar = t >> 2, ak = (t & 3) * 4;
    int bk = t >> 4, bc = (t & 15) * 4;
    int rb = blockIdx.y * 64, cb = blockIdx.x * 64;

    float acc[4][4];
    #pragma unroll
    for (int i = 0; i < 4; i++)
        #pragma unroll
        for (int jj = 0; jj < 4; jj++) acc[i][jj] = 0.f;

    for (int kt = 0; kt < IN_; kt += 16) {
        float4 av = *(const float4*)(Xi + (rb + ar) * IN_ + kt + ak);
        int c0 = cb + bc;
        float4 bv = *(const float4*)(Wq + (c0 >> 4) * (IN_ * AN) + (kt + bk) * AN + (c0 & 15));
        As[ak + 0][ar] = av.x; As[ak + 1][ar] = av.y;
        As[ak + 2][ar] = av.z; As[ak + 3][ar] = av.w;
        *(float4*)&Bs[bk][bc] = bv;
        __syncthreads();
        #pragma unroll
        for (int k = 0; k < 16; k++) {
            float4 a = *(const float4*)&As[k][ty * 4];
            float4 b = *(const float4*)&Bs[k][tx * 4];
            float arr[4] = {a.x, a.y, a.z, a.w};
            float brr[4] = {b.x, b.y, b.z, b.w};
            #pragma unroll
            for (int i = 0; i < 4; i++)
                #pragma unroll
                for (int jj = 0; jj < 4; jj++) acc[i][jj] += arr[i] * brr[jj];
        }
        __syncthreads();
    }
    #pragma unroll
    for (int i = 0; i < 4; i++)
        #pragma unroll
        for (int jj = 0; jj < 4; jj++)
            g_Qa[(rb + ty * 4 + i) * DN + cb + tx * 4 + jj] = acc[i][jj];
}

// -------- K|V = Si @ [Wk|Wv] -> g_KV [8192 x 256] --------
__global__ void __launch_bounds__(256) k_gemmKV(const float* __restrict__ Si,
                                                const float* __restrict__ Wk,
                                                const float* __restrict__ Wv) {
    __shared__ float As[16][64];
    __shared__ float Bs[16][64];
    int t = threadIdx.x;
    int tx = t & 15, ty = t >> 4;
    int ar = t >> 2, ak = (t & 3) * 4;
    int bk = t >> 4, bc = (t & 15) * 4;
    int rb = blockIdx.y * 64, cb = blockIdx.x * 64;

    float acc[4][4];
    #pragma unroll
    for (int i = 0; i < 4; i++)
        #pragma unroll
        for (int jj = 0; jj < 4; jj++) acc[i][jj] = 0.f;

    for (int kt = 0; kt < RN; kt += 16) {
        float4 av = *(const float4*)(Si + (rb + ar) * RN + kt + ak);
        int c0 = cb + bc;
        const float* base = (c0 < 128) ? Wk : Wv;
        int cl = c0 & 127;
        float4 bv = *(const float4*)(base + (cl >> 4) * (RN * AN) + (kt + bk) * AN + (cl & 15));
        As[ak + 0][ar] = av.x; As[ak + 1][ar] = av.y;
        As[ak + 2][ar] = av.z; As[ak + 3][ar] = av.w;
        *(float4*)&Bs[bk][bc] = bv;
        __syncthreads();
        #pragma unroll
        for (int k = 0; k < 16; k++) {
            float4 a = *(const float4*)&As[k][ty * 4];
            float4 b = *(const float4*)&Bs[k][tx * 4];
            float arr[4] = {a.x, a.y, a.z, a.w};
            float brr[4] = {b.x, b.y, b.z, b.w};
            #pragma unroll
            for (int i = 0; i < 4; i++)
                #pragma unroll
                for (int jj = 0; jj < 4; jj++) acc[i][jj] += arr[i] * brr[jj];
        }
        __syncthreads();
    }
    #pragma unroll
    for (int i = 0; i < 4; i++)
        #pragma unroll
        for (int jj = 0; jj < 4; jj++)
            g_KV[(rb + ty * 4 + i) * 256 + cb + tx * 4 + jj] = acc[i][jj];
}

// -------- attention: scores -> softmax -> /sqrt(D) -> Ui --------
__global__ void k_attn() {
    int idx = blockIdx.x * blockDim.x + threadIdx.x;
    if (idx >= BN * MU * MU) return;
    int b = idx >> 6;
    int m = (idx >> 3) & 7;
    int q = idx & 7;

    float qv[AN];
    const float* Qp = g_Qa + b * DN + q * AN;
    #pragma unroll
    for (int a = 0; a < AN; a++) qv[a] = Qp[a];

    float s[MU];
    #pragma unroll
    for (int n = 0; n < MU; n++) {
        const float* Kp = g_KV + (b * MU + n) * 256 + m * AN;
        float d = 0.f;
        #pragma unroll
        for (int a = 0; a < AN; a++) d += qv[a] * Kp[a];
        s[n] = d;
    }
    float mx = s[0];
    #pragma unroll
    for (int n = 1; n < MU; n++) mx = fmaxf(mx, s[n]);
    float sum = 0.f;
    #pragma unroll
    for (int n = 0; n < MU; n++) { s[n] = __expf(s[n] - mx); sum += s[n]; }
    float scale = 1.0f / (sum * sqrtf((float)DN));
    #pragma unroll
    for (int n = 0; n < MU; n++) s[n] *= scale;

    float* Up = g_Ui + (b * MU + m) * DN + q * AN;
    #pragma unroll
    for (int a = 0; a < AN; a++) {
        float u = 0.f;
        #pragma unroll
        for (int n = 0; n < MU; n++)
            u += s[n] * g_KV[(b * MU + n) * 256 + 128 + m * AN + a];
        Up[a] = u;
    }
}

// -------- state update: Snew = (1-lr)Si + lr*tanh(Ui@Win + Si@(W*sc) + bias) --------
// concat-K GEMM, KC=16, double-buffered, f32x2 col-pairs. grid (4,8,8), 256 thr.
__global__ void __launch_bounds__(256, 2) k_state(const float* __restrict__ Si,
                                                  const float* __restrict__ Win,
                                                  const float* __restrict__ W,
                                                  const float* __restrict__ bias,
                                                  const float* __restrict__ lr,
                                                  float* __restrict__ Snew) {
    int m = blockIdx.z;
    float scm = g_sc[m];
    float lrm = lr[m];

    __shared__ float As[2][KC][128];
    __shared__ float Bs[2][KC][128];

    int t  = threadIdx.x;
    int tx = t & 15, ty = t >> 4;
    int rowBase = blockIdx.y * 128;
    int colBase = blockIdx.x * 128;

    int ar = t & 127;
    int aq = (t >> 7) * 8;

    uint64_t acc[8][4];
    #pragma unroll
    for (int i = 0; i < 8; i++)
        #pragma unroll
        for (int jp = 0; jp < 4; jp++) acc[i][jp] = 0ull;

    float4 pa[2], pb[2];
    // load chunk 0
    #pragma unroll
    for (int q = 0; q < 2; q++) {
        int kA = aq + q * 4;
        pa[q] = *(const float4*)(g_Ui + ((rowBase + ar) * MU + m) * DN + kA);
    }
    #pragma unroll
    for (int q = 0; q < 2; q++) {
        int f = t + q * 256;
        int kB = f >> 5, c4 = (f & 31) * 4;
        pb[q] = *(const float4*)(Win + m * (DN * RN) + kB * RN + colBase + c4);
    }
    #pragma unroll
    for (int q = 0; q < 2; q++) {
        As[0][aq + q * 4 + 0][ar] = pa[q].x; As[0][aq + q * 4 + 1][ar] = pa[q].y;
        As[0][aq + q * 4 + 2][ar] = pa[q].z; As[0][aq + q * 4 + 3][ar] = pa[q].w;
        int f = t + q * 256;
        *(float4*)&Bs[0][f >> 5][(f & 31) * 4] = pb[q];
    }
    __syncthreads();

    const int NCH = (DN + RN) / KC;   // 40
    for (int c = 0; c < NCH; c++) {
        int buf = c & 1, nxt = buf ^ 1;
        if (c + 1 < NCH) {
            int kn = (c + 1) * KC;
            #pragma unroll
            for (int q = 0; q < 2; q++) {
                int kA = kn + aq + q * 4;
                int brow = rowBase + ar;
                if (kA < DN)
                    pa[q] = *(const float4*)(g_Ui + (brow * MU + m) * DN + kA);
                else
                    pa[q] = *(const float4*)(Si + brow * (MU * RN) + m * RN + (kA - DN));
            }
            #pragma unroll
            for (int q = 0; q < 2; q++) {
                int f = t + q * 256;
                int kB = kn + (f >> 5);
                int c4 = (f & 31) * 4;
                if (kB < DN) {
                    pb[q] = *(const float4*)(Win + m * (DN * RN) + kB * RN + colBase + c4);
                } else {
                    pb[q] = *(const float4*)(W + m * (RN * RN) + (kB - DN) * RN + colBase + c4);
                    pb[q].x *= scm; pb[q].y *= scm; pb[q].z *= scm; pb[q].w *= scm;
                }
            }
        }

        #pragma unroll
        for (int k = 0; k < KC; k++) {
            float4 a0 = *(const float4*)&As[buf][k][ty * 8];
            float4 a1 = *(const float4*)&As[buf][k][ty * 8 + 4];
            float4 b0 = *(const float4*)&Bs[buf][k][tx * 8];
            float4 b1 = *(const float4*)&Bs[buf][k][tx * 8 + 4];
            uint64_t bp[4];
            bp[0] = pack2(b0.x, b0.y); bp[1] = pack2(b0.z, b0.w);
            bp[2] = pack2(b1.x, b1.y); bp[3] = pack2(b1.z, b1.w);
            float av[8] = {a0.x, a0.y, a0.z, a0.w, a1.x, a1.y, a1.z, a1.w};
            #pragma unroll
            for (int i = 0; i < 8; i++) {
                uint64_t ai = pack2(av[i], av[i]);
                #pragma unroll
                for (int jp = 0; jp < 4; jp++) ffma2(acc[i][jp], ai, bp[jp]);
            }
        }

        if (c + 1 < NCH) {
            #pragma unroll
            for (int q = 0; q < 2; q++) {
                As[nxt][aq + q * 4 + 0][ar] = pa[q].x;
                As[nxt][aq + q * 4 + 1][ar] = pa[q].y;
                As[nxt][aq + q * 4 + 2][ar] = pa[q].z;
                As[nxt][aq + q * 4 + 3][ar] = pa[q].w;
                int f = t + q * 256;
                *(float4*)&Bs[nxt][f >> 5][(f & 31) * 4] = pb[q];
            }
        }
        __syncthreads();
    }

    #pragma unroll
    for (int i = 0; i < 8; i++) {
        int b = rowBase + ty * 8 + i;
        #pragma unroll
        for (int jp = 0; jp < 4; jp++) {
            float lo, hi;
            unpack2(acc[i][jp], lo, hi);
            int r0 = colBase + tx * 8 + 2 * jp;
            float x0 = lo + bias[m * RN + r0];
            float x1 = hi + bias[m * RN + r0 + 1];
            float s0 = Si[b * (MU * RN) + m * RN + r0];
            float s1 = Si[b * (MU * RN) + m * RN + r0 + 1];
            Snew[b * (MU * RN) + m * RN + r0]     = (1.0f - lrm) * s0 + lrm * tanhf(x0);
            Snew[b * (MU * RN) + m * RN + r0 + 1] = (1.0f - lrm) * s1 + lrm * tanhf(x1);
        }
    }
}

// -------- Yi partials: g_Yp[z] = Snew[:, z*1024:(z+1)*1024] @ Wout[z*1024:...] --------
// 128x128 tile, 256 thr, f32x2 col-pairs, double-buffered. grid (4,8,4) = 128 CTAs.
__global__ void __launch_bounds__(256, 1) k_gemmYi_p(const float* __restrict__ Snew,
                                                     const float* __restrict__ Wout) {
    const int K = MU * RN;            // 4096
    const int KSEG = K / 4;           // 1024
    int z = blockIdx.z;
    int k0 = z * KSEG;
    float* dst = g_Yp[z];

    __shared__ float As[2][KC][128];
    __shared__ float Bs[2][KC][128];

    int t  = threadIdx.x;
    int tx = t & 15, ty = t >> 4;
    int rowBase = blockIdx.y * 128;
    int colBase = blockIdx.x * 128;

    int ar = t & 127;
    int aq = (t >> 7) * 8;

    uint64_t acc[8][4];
    #pragma unroll
    for (int i = 0; i < 8; i++)
        #pragma unroll
        for (int jp = 0; jp < 4; jp++) acc[i][jp] = 0ull;

    float4 pa[2], pb[2];
    #pragma unroll
    for (int q = 0; q < 2; q++)
        pa[q] = *(const float4*)(Snew + (rowBase + ar) * K + k0 + aq + q * 4);
    #pragma unroll
    for (int q = 0; q < 2; q++) {
        int f = t + q * 256;
        pb[q] = *(const float4*)(Wout + (k0 + (f >> 5)) * ON + colBase + (f & 31) * 4);
    }
    #pragma unroll
    for (int q = 0; q < 2; q++) {
        As[0][aq + q * 4 + 0][ar] = pa[q].x; As[0][aq + q * 4 + 1][ar] = pa[q].y;
        As[0][aq + q * 4 + 2][ar] = pa[q].z; As[0][aq + q * 4 + 3][ar] = pa[q].w;
        int f = t + q * 256;
        *(float4*)&Bs[0][f >> 5][(f & 31) * 4] = pb[q];
    }
    __syncthreads();

    const int NCH = KSEG / KC;   // 64
    for (int c = 0; c < NCH; c++) {
        int buf = c & 1, nxt = buf ^ 1;
        if (c + 1 < NCH) {
            int kn = k0 + (c + 1) * KC;
            #pragma unroll
            for (int q = 0; q < 2; q++)
                pa[q] = *(const float4*)(Snew + (rowBase + ar) * K + kn + aq + q * 4);
            #pragma unroll
            for (int q = 0; q < 2; q++) {
                int f = t + q * 256;
                pb[q] = *(const float4*)(Wout + (kn + (f >> 5)) * ON + colBase + (f & 31) * 4);
            }
        }

        #pragma unroll
        for (int k = 0; k < KC; k++) {
            float4 a0 = *(const float4*)&As[buf][k][ty * 8];
            float4 a1 = *(const float4*)&As[buf][k][ty * 8 + 4];
            float4 b0 = *(const float4*)&Bs[buf][k][tx * 8];
            float4 b1 = *(const float4*)&Bs[buf][k][tx * 8 + 4];
            uint64_t bp[4];
            bp[0] = pack2(b0.x, b0.y); bp[1] = pack2(b0.z, b0.w);
            bp[2] = pack2(b1.x, b1.y); bp[3] = pack2(b1.z, b1.w);
            float av[8] = {a0.x, a0.y, a0.z, a0.w, a1.x, a1.y, a1.z, a1.w};
            #pragma unroll
            for (int i = 0; i < 8; i++) {
                uint64_t ai = pack2(av[i], av[i]);
                #pragma unroll
                for (int jp = 0; jp < 4; jp++) ffma2(acc[i][jp], ai, bp[jp]);
            }
        }

        if (c + 1 < NCH) {
            #pragma unroll
            for (int q = 0; q < 2; q++) {
                As[nxt][aq + q * 4 + 0][ar] = pa[q].x;
                As[nxt][aq + q * 4 + 1][ar] = pa[q].y;
                As[nxt][aq + q * 4 + 2][ar] = pa[q].z;
                As[nxt][aq + q * 4 + 3][ar] = pa[q].w;
                int f = t + q * 256;
                *(float4*)&Bs[nxt][f >> 5][(f & 31) * 4] = pb[q];
            }
        }
        __syncthreads();
    }

    #pragma unroll
    for (int i = 0; i < 8; i++) {
        int gr = rowBase + ty * 8 + i;
        float cv[8];
        #pragma unroll
        for (int jp = 0; jp < 4; jp++)
            unpack2(acc[i][jp], cv[2 * jp], cv[2 * jp + 1]);
        *(float4*)(dst + gr * ON + colBase + tx * 8)     = make_float4(cv[0], cv[1], cv[2], cv[3]);
        *(float4*)(dst + gr * ON + colBase + tx * 8 + 4) = make_float4(cv[4], cv[5], cv[6], cv[7]);
    }
}

// -------- Yi = sum of 4 split-K partials (deterministic fixed order) --------
__global__ void k_yred(float* __restrict__ Yi) {
    int i = (blockIdx.x * blockDim.x + threadIdx.x) * 4;
    float4 a = *(const float4*)(g_Yp[0] + i);
    float4 b = *(const float4*)(g_Yp[1] + i);
    float4 c = *(const float4*)(g_Yp[2] + i);
    float4 d = *(const float4*)(g_Yp[3] + i);
    float4 o;
    o.x = (a.x + b.x) + (c.x + d.x);
    o.y = (a.y + b.y) + (c.y + d.y);
    o.z = (a.z + b.z) + (c.z + d.z);
    o.w = (a.w + b.w) + (c.w + d.w);
    *(float4*)(Yi + i) = o;
}

// ------------------------------------------------------------------
extern "C" void kernel_launch(void* const* d_in, const int* in_sizes, int n_in,
                              void* d_out, int out_size) {
    const float* Xi   = (const float*)d_in[0];
    const float* Si   = (const float*)d_in[1];
    const float* Wq   = (const float*)d_in[2];
    const float* Wk   = (const float*)d_in[3];
    const float* Wv   = (const float*)d_in[4];
    const float* Wout = (const float*)d_in[5];
    const float* W    = (const float*)d_in[6];
    const float* Win  = (const float*)d_in[7];
    const float* bias = (const float*)d_in[8];
    const float* sr   = (const float*)d_in[9];
    const float* lr   = (const float*)d_in[10];

    float* Yi   = (float*)d_out;
    float* Snew = (float*)d_out + BN * ON;

    // --- spectral radius via normalized repeated squaring ---
    k_init<<<1, 256>>>();
    k_norm0<<<dim3(16, 8), 256>>>(W);
    for (int j = 0; j < NSQ; j++)
        k_sqr<<<dim3(4, 4, 8), 256>>>(W, j);
    k_finalize<<<1, 32>>>(sr);

    // --- attention path ---
    k_gemmQ<<<dim3(2, 16), 256>>>(Xi, Wq);
    k_gemmKV<<<dim3(4, 128), 256>>>(Si, Wk, Wv);
    k_attn<<<BN * MU * MU / 256, 256>>>();

    // --- reservoir state update (fused feed+echo+tanh+leak) ---
    k_state<<<dim3(4, 8, 8), 256>>>(Si, Win, W, bias, lr, Snew);

    // --- readout: split-K partials + deterministic reduce ---
    k_gemmYi_p<<<dim3(4, 8, 4), 256>>>(Snew, Wout);
    k_yred<<<BN * ON / 1024, 256>>>(Yi);
}